// round 2
// baseline (speedup 1.0000x reference)
#include <cuda_runtime.h>
#include <math.h>

#define TT 256
#define NROW 2048            // B*T
#define BN_EPS 1e-5f

// qkv scratch: [2048][192] (q|k|v)
__device__ float g_qkv[NROW * 192];

// ---------------------------------------------------------------------------
// Kernel 1: qkv = x @ w_qkv   ([2048,128] x [128,192])
// ---------------------------------------------------------------------------
__global__ __launch_bounds__(192) void qkv_kernel(const float* __restrict__ x,
                                                  const float* __restrict__ w) {
    __shared__ float xs[128];
    const int row = blockIdx.x;
    const int tid = threadIdx.x;     // 0..191
    if (tid < 128) xs[tid] = x[row * 128 + tid];
    __syncthreads();
    float a0 = 0.f, a1 = 0.f, a2 = 0.f, a3 = 0.f;
#pragma unroll 8
    for (int d = 0; d < 128; d += 4) {
        a0 += xs[d + 0] * w[(d + 0) * 192 + tid];
        a1 += xs[d + 1] * w[(d + 1) * 192 + tid];
        a2 += xs[d + 2] * w[(d + 2) * 192 + tid];
        a3 += xs[d + 3] * w[(d + 3) * 192 + tid];
    }
    g_qkv[row * 192 + tid] = (a0 + a1) + (a2 + a3);
}

// ---------------------------------------------------------------------------
// Kernel 2: one block per (b,i) row. 256 threads.
// Shared layout (float offsets):
// ---------------------------------------------------------------------------
#define OFF_W1F 0        // 9*32 = 288  (BN-folded tpr_w1)
#define OFF_B1F 288      // 32         (BN-folded bias)
#define OFF_W2T 320      // 32*64
#define OFF_B2F 2368     // 64
#define OFF_W1A 2432     // 64*64
#define OFF_B1A 6528     // 64
#define OFF_W2A 6592     // 64*64
#define OFF_B2A 10688    // 64
#define OFF_QS  10752    // 64
#define OFF_RT  10816    // 64*9 = 576 (r tile)
#define OFF_H   11392    // 64*36 (padded)
#define OFF_RE  13696    // 64*68 (padded)
#define OFF_TB  18048    // 64*68 (padded)  -- aliased as reduction buf at end
#define OFF_S1  22400    // 64*68 (padded)
#define SMEM_FLOATS 26752
#define SMEM_BYTES (SMEM_FLOATS * 4)

__global__ __launch_bounds__(256) void va_kernel(
    const float* __restrict__ r,
    const float* __restrict__ tpr_w1, const float* __restrict__ tpr_b1,
    const float* __restrict__ bn_g, const float* __restrict__ bn_b,
    const float* __restrict__ bn_m, const float* __restrict__ bn_v,
    const float* __restrict__ tpr_w2, const float* __restrict__ tpr_b2,
    const float* __restrict__ aw1, const float* __restrict__ ab1,
    const float* __restrict__ aw2, const float* __restrict__ ab2,
    float* __restrict__ out)
{
    extern __shared__ float sm[];
    const int tid = threadIdx.x;
    const int row = blockIdx.x;          // b*T + i
    const int b = row >> 8;

    // ---- stage weights (BN folded into W1F/B1F) ----
    for (int idx = tid; idx < 288; idx += 256) {
        int ch = idx & 31;
        float sc = bn_g[ch] * rsqrtf(bn_v[ch] + BN_EPS);
        sm[OFF_W1F + idx] = tpr_w1[idx] * sc;
    }
    if (tid < 32) {
        float sc = bn_g[tid] * rsqrtf(bn_v[tid] + BN_EPS);
        sm[OFF_B1F + tid] = (tpr_b1[tid] - bn_m[tid]) * sc + bn_b[tid];
    }
    for (int idx = tid; idx < 2048; idx += 256) sm[OFF_W2T + idx] = tpr_w2[idx];
    for (int idx = tid; idx < 4096; idx += 256) sm[OFF_W1A + idx] = aw1[idx];
    for (int idx = tid; idx < 4096; idx += 256) sm[OFF_W2A + idx] = aw2[idx];
    if (tid < 64) {
        sm[OFF_B2F + tid] = tpr_b2[tid];
        sm[OFF_B1A + tid] = ab1[tid];
        sm[OFF_B2A + tid] = ab2[tid];
        sm[OFF_QS + tid]  = g_qkv[row * 192 + tid];
    }
    __syncthreads();

    const int jr = tid >> 4;             // 0..15  (j rows of 4)
    const int c0 = (tid & 15) << 2;      // 0..60  (4 channels)

    float m4[4], l4[4], a4[4];
#pragma unroll
    for (int u = 0; u < 4; u++) { m4[u] = -1e30f; l4[u] = 0.f; a4[u] = 0.f; }

    const float* rrow = r + (size_t)row * (TT * 9);

    for (int jt = 0; jt < 4; jt++) {
        const int j0 = jt * 64;
        // ---- stage r tile ----
        for (int idx = tid; idx < 576; idx += 256)
            sm[OFF_RT + idx] = rrow[j0 * 9 + idx];
        __syncthreads();

        // ---- Phase A: H = relu(r @ W1F + B1F)  [64 x 32] ----
        {
            const int lj = tid >> 2;
            const int h0 = (tid & 3) << 3;
            float rv[9];
#pragma unroll
            for (int d = 0; d < 9; d++) rv[d] = sm[OFF_RT + lj * 9 + d];
#pragma unroll
            for (int u = 0; u < 8; u++) {
                const int h = h0 + u;
                float acc = sm[OFF_B1F + h];
#pragma unroll
                for (int d = 0; d < 9; d++) acc += rv[d] * sm[OFF_W1F + d * 32 + h];
                sm[OFF_H + lj * 36 + h] = fmaxf(acc, 0.f);
            }
        }
        __syncthreads();

        // ---- Phase B: RelEmb = H @ W2T + b2 ;  T = q - k + RelEmb ----
        {
            float acc[4][4];
#pragma unroll
            for (int i = 0; i < 4; i++)
#pragma unroll
                for (int u = 0; u < 4; u++) acc[i][u] = 0.f;
#pragma unroll 8
            for (int k = 0; k < 32; k++) {
                const float4 bv = *(const float4*)&sm[OFF_W2T + k * 64 + c0];
#pragma unroll
                for (int i = 0; i < 4; i++) {
                    const float a = sm[OFF_H + (jr * 4 + i) * 36 + k];
                    acc[i][0] += a * bv.x; acc[i][1] += a * bv.y;
                    acc[i][2] += a * bv.z; acc[i][3] += a * bv.w;
                }
            }
            const float4 bb = *(const float4*)&sm[OFF_B2F + c0];
            const float4 qv = *(const float4*)&sm[OFF_QS + c0];
#pragma unroll
            for (int i = 0; i < 4; i++) {
                const int lj = jr * 4 + i;
                const int gj = j0 + lj;
                const float4 kg = *(const float4*)&g_qkv[(b * TT + gj) * 192 + 64 + c0];
                const float re0 = acc[i][0] + bb.x, re1 = acc[i][1] + bb.y;
                const float re2 = acc[i][2] + bb.z, re3 = acc[i][3] + bb.w;
                *(float4*)&sm[OFF_RE + lj * 68 + c0] = make_float4(re0, re1, re2, re3);
                *(float4*)&sm[OFF_TB + lj * 68 + c0] =
                    make_float4(qv.x - kg.x + re0, qv.y - kg.y + re1,
                                qv.z - kg.z + re2, qv.w - kg.w + re3);
            }
        }
        __syncthreads();

        // ---- Phase C: S1 = relu(T @ W1A + b1) ----
        {
            float acc[4][4];
#pragma unroll
            for (int i = 0; i < 4; i++)
#pragma unroll
                for (int u = 0; u < 4; u++) acc[i][u] = 0.f;
#pragma unroll 8
            for (int k = 0; k < 64; k++) {
                const float4 bv = *(const float4*)&sm[OFF_W1A + k * 64 + c0];
#pragma unroll
                for (int i = 0; i < 4; i++) {
                    const float a = sm[OFF_TB + (jr * 4 + i) * 68 + k];
                    acc[i][0] += a * bv.x; acc[i][1] += a * bv.y;
                    acc[i][2] += a * bv.z; acc[i][3] += a * bv.w;
                }
            }
            const float4 bb = *(const float4*)&sm[OFF_B1A + c0];
#pragma unroll
            for (int i = 0; i < 4; i++) {
                const int lj = jr * 4 + i;
                *(float4*)&sm[OFF_S1 + lj * 68 + c0] =
                    make_float4(fmaxf(acc[i][0] + bb.x, 0.f), fmaxf(acc[i][1] + bb.y, 0.f),
                                fmaxf(acc[i][2] + bb.z, 0.f), fmaxf(acc[i][3] + bb.w, 0.f));
            }
        }
        __syncthreads();

        // ---- Phase D: Sim = S1 @ W2A + b2 ; online softmax accumulate ----
        {
            float acc[4][4];
#pragma unroll
            for (int i = 0; i < 4; i++)
#pragma unroll
                for (int u = 0; u < 4; u++) acc[i][u] = 0.f;
#pragma unroll 8
            for (int k = 0; k < 64; k++) {
                const float4 bv = *(const float4*)&sm[OFF_W2A + k * 64 + c0];
#pragma unroll
                for (int i = 0; i < 4; i++) {
                    const float a = sm[OFF_S1 + (jr * 4 + i) * 68 + k];
                    acc[i][0] += a * bv.x; acc[i][1] += a * bv.y;
                    acc[i][2] += a * bv.z; acc[i][3] += a * bv.w;
                }
            }
            const float4 bb = *(const float4*)&sm[OFF_B2A + c0];
#pragma unroll
            for (int i = 0; i < 4; i++) {
                const int lj = jr * 4 + i;
                const int gj = j0 + lj;
                const float4 vg = *(const float4*)&g_qkv[(b * TT + gj) * 192 + 128 + c0];
                const float4 re = *(const float4*)&sm[OFF_RE + lj * 68 + c0];
                float s[4] = { acc[i][0] + bb.x, acc[i][1] + bb.y,
                               acc[i][2] + bb.z, acc[i][3] + bb.w };
                float vj[4] = { vg.x + re.x, vg.y + re.y, vg.z + re.z, vg.w + re.w };
#pragma unroll
                for (int u = 0; u < 4; u++) {
                    const float nm = fmaxf(m4[u], s[u]);
                    const float f = __expf(m4[u] - nm);
                    const float e = __expf(s[u] - nm);
                    l4[u] = l4[u] * f + e;
                    a4[u] = a4[u] * f + e * vj[u];
                    m4[u] = nm;
                }
            }
        }
        // next-iteration leading __syncthreads() orders Phase D reads vs. new writes
    }

    // ---- cross-jr softmax combine (reduction buf aliases OFF_TB) ----
#pragma unroll
    for (int u = 0; u < 4; u++) {
        sm[OFF_TB +        jr * 64 + c0 + u] = m4[u];
        sm[OFF_TB + 1024 + jr * 64 + c0 + u] = l4[u];
        sm[OFF_TB + 2048 + jr * 64 + c0 + u] = a4[u];
    }
    __syncthreads();
    if (tid < 64) {
        float M = -1e30f;
#pragma unroll
        for (int p = 0; p < 16; p++) M = fmaxf(M, sm[OFF_TB + p * 64 + tid]);
        float L = 0.f, A = 0.f;
#pragma unroll
        for (int p = 0; p < 16; p++) {
            const float f = __expf(sm[OFF_TB + p * 64 + tid] - M);
            L += sm[OFF_TB + 1024 + p * 64 + tid] * f;
            A += sm[OFF_TB + 2048 + p * 64 + tid] * f;
        }
        out[row * 64 + tid] = A / L;
    }
}

// ---------------------------------------------------------------------------
extern "C" void kernel_launch(void* const* d_in, const int* in_sizes, int n_in,
                              void* d_out, int out_size) {
    (void)in_sizes; (void)n_in; (void)out_size;
    const float* x      = (const float*)d_in[0];
    const float* r      = (const float*)d_in[1];
    const float* w_qkv  = (const float*)d_in[2];
    const float* tpr_w1 = (const float*)d_in[3];
    const float* tpr_b1 = (const float*)d_in[4];
    const float* bn_g   = (const float*)d_in[5];
    const float* bn_b   = (const float*)d_in[6];
    const float* bn_m   = (const float*)d_in[7];
    const float* bn_v   = (const float*)d_in[8];
    const float* tpr_w2 = (const float*)d_in[9];
    const float* tpr_b2 = (const float*)d_in[10];
    const float* aw1    = (const float*)d_in[11];
    const float* ab1    = (const float*)d_in[12];
    const float* aw2    = (const float*)d_in[13];
    const float* ab2    = (const float*)d_in[14];
    float* out = (float*)d_out;

    // idempotent, not a stream op -> invisible to graph capture, deterministic
    cudaFuncSetAttribute(va_kernel, cudaFuncAttributeMaxDynamicSharedMemorySize,
                         SMEM_BYTES);

    qkv_kernel<<<NROW, 192>>>(x, w_qkv);
    va_kernel<<<NROW, 256, SMEM_BYTES>>>(r, tpr_w1, tpr_b1, bn_g, bn_b, bn_m, bn_v,
                                         tpr_w2, tpr_b2, aw1, ab1, aw2, ab2, out);
}

// round 3
// speedup vs baseline: 1.2667x; 1.2667x over previous
#include <cuda_runtime.h>
#include <math.h>

#define TT 256
#define NROW 2048            // B*T
#define BN_EPS 1e-5f

// scratch
__device__ float g_qkv[NROW * 192];    // q|k|v per row
__device__ float g_proj[NROW * 128];   // qA|kA per row  ({q,k}@attn_w1)
__device__ float g_w2p[32 * 64];       // tpr_w2 @ attn_w1
__device__ float g_b1a[64];            // tpr_b2 @ attn_w1 + attn_b1

// ---------------------------------------------------------------------------
// Kernel 1: qkv = x @ w_qkv   ([2048,128] x [128,192])
// ---------------------------------------------------------------------------
__global__ __launch_bounds__(192) void qkv_kernel(const float* __restrict__ x,
                                                  const float* __restrict__ w) {
    __shared__ float xs[128];
    const int row = blockIdx.x;
    const int tid = threadIdx.x;
    if (tid < 128) xs[tid] = x[row * 128 + tid];
    __syncthreads();
    float a0 = 0.f, a1 = 0.f, a2 = 0.f, a3 = 0.f;
#pragma unroll 8
    for (int d = 0; d < 128; d += 4) {
        a0 += xs[d + 0] * w[(d + 0) * 192 + tid];
        a1 += xs[d + 1] * w[(d + 1) * 192 + tid];
        a2 += xs[d + 2] * w[(d + 2) * 192 + tid];
        a3 += xs[d + 3] * w[(d + 3) * 192 + tid];
    }
    g_qkv[row * 192 + tid] = (a0 + a1) + (a2 + a3);
}

// ---------------------------------------------------------------------------
// Kernel 1b: qA = q@Aw1, kA = k@Aw1 per row
// ---------------------------------------------------------------------------
__global__ __launch_bounds__(128) void proj_kernel(const float* __restrict__ aw1) {
    __shared__ float qk[128];
    const int row = blockIdx.x;
    const int tid = threadIdx.x;     // 0..127
    qk[tid] = g_qkv[row * 192 + tid];
    __syncthreads();
    const float* src = (tid < 64) ? qk : (qk + 64);
    const int col = tid & 63;
    float a0 = 0.f, a1 = 0.f;
#pragma unroll 8
    for (int d = 0; d < 64; d += 2) {
        a0 += src[d + 0] * aw1[(d + 0) * 64 + col];
        a1 += src[d + 1] * aw1[(d + 1) * 64 + col];
    }
    g_proj[row * 128 + tid] = a0 + a1;
}

// ---------------------------------------------------------------------------
// Kernel 1c: W2P = tpr_w2 @ attn_w1 [32,64]; b1a = tpr_b2 @ attn_w1 + attn_b1
// ---------------------------------------------------------------------------
__global__ __launch_bounds__(64) void w2p_kernel(const float* __restrict__ tpr_w2,
                                                 const float* __restrict__ tpr_b2,
                                                 const float* __restrict__ aw1,
                                                 const float* __restrict__ ab1) {
    __shared__ float w2s[2048];
    __shared__ float a1s[4096];
    const int tid = threadIdx.x;     // 0..63
    for (int i = tid; i < 2048; i += 64) w2s[i] = tpr_w2[i];
    for (int i = tid; i < 4096; i += 64) a1s[i] = aw1[i];
    __syncthreads();
    const int c = tid;
    for (int h = 0; h < 32; h++) {
        float acc = 0.f;
#pragma unroll 8
        for (int d = 0; d < 64; d++) acc += w2s[h * 64 + d] * a1s[d * 64 + c];
        g_w2p[h * 64 + c] = acc;
    }
    float accb = ab1[c];
#pragma unroll 8
    for (int d = 0; d < 64; d++) accb += tpr_b2[d] * a1s[d * 64 + c];
    g_b1a[c] = accb;
}

// ---------------------------------------------------------------------------
// Main kernel: one block per (b,i) row. 256 threads, 3 CTAs/SM.
// Shared layout (float offsets):
// ---------------------------------------------------------------------------
#define OFF_W1F 0        // 9*32 (BN-folded tpr_w1)
#define OFF_B1F 288      // 32
#define OFF_W2T 320      // 32*64 (tpr_w2)
#define OFF_W2P 2368     // 32*64 (tpr_w2 @ attn_w1)
#define OFF_W2A 4416     // 64*64 (attn_w2)
#define OFF_B2F 8512     // 64 (tpr_b2)
#define OFF_B1A 8576     // 64 (folded)
#define OFF_B2A 8640     // 64 (attn_b2)
#define OFF_QA  8704     // 64 (this row's q@Aw1)
#define OFF_RT  8768     // 64*9 r tile
#define OFF_H   9344     // 64*36 padded
#define OFF_S1  11648    // 64*68 padded
#define SMEM_FLOATS 16000
#define SMEM_BYTES (SMEM_FLOATS * 4)

__global__ __launch_bounds__(256, 3) void va_kernel(
    const float* __restrict__ r,
    const float* __restrict__ tpr_w1, const float* __restrict__ tpr_b1,
    const float* __restrict__ bn_g, const float* __restrict__ bn_b,
    const float* __restrict__ bn_m, const float* __restrict__ bn_v,
    const float* __restrict__ tpr_w2, const float* __restrict__ tpr_b2,
    const float* __restrict__ aw2, const float* __restrict__ ab2,
    float* __restrict__ out)
{
    extern __shared__ float sm[];
    const int tid = threadIdx.x;
    const int row = blockIdx.x;          // b*T + i
    const int b = row >> 8;

    // ---- stage weights ----
    for (int idx = tid; idx < 288; idx += 256) {
        int ch = idx & 31;
        float sc = bn_g[ch] * rsqrtf(bn_v[ch] + BN_EPS);
        sm[OFF_W1F + idx] = tpr_w1[idx] * sc;
    }
    if (tid < 32) {
        float sc = bn_g[tid] * rsqrtf(bn_v[tid] + BN_EPS);
        sm[OFF_B1F + tid] = (tpr_b1[tid] - bn_m[tid]) * sc + bn_b[tid];
    }
    for (int idx = tid; idx < 2048; idx += 256) {
        sm[OFF_W2T + idx] = tpr_w2[idx];
        sm[OFF_W2P + idx] = g_w2p[idx];
    }
    for (int idx = tid; idx < 4096; idx += 256) sm[OFF_W2A + idx] = aw2[idx];
    if (tid < 64) {
        sm[OFF_B2F + tid] = tpr_b2[tid];
        sm[OFF_B1A + tid] = g_b1a[tid];
        sm[OFF_B2A + tid] = ab2[tid];
        sm[OFF_QA + tid]  = g_proj[row * 128 + tid];   // qA
    }

    const int jr = tid >> 4;             // 0..15  (j rows of 4)
    const int c0 = (tid & 15) << 2;      // 0..60  (4 channels)

    float m4[4], l4[4], a4[4];
#pragma unroll
    for (int u = 0; u < 4; u++) { m4[u] = -1e30f; l4[u] = 0.f; a4[u] = 0.f; }

    const float* rrow = r + (size_t)row * (TT * 9);

    for (int jt = 0; jt < 4; jt++) {
        const int j0 = jt * 64;
        __syncthreads();    // prev-iter reads of RT/S1 done; weights visible on jt=0
        for (int idx = tid; idx < 576; idx += 256)
            sm[OFF_RT + idx] = rrow[j0 * 9 + idx];
        __syncthreads();

        // ---- Phase A: H = relu(r @ W1F + B1F)  [64 x 32] ----
        {
            const int lj = tid >> 2;
            const int h0 = (tid & 3) << 3;
            float rv[9];
#pragma unroll
            for (int d = 0; d < 9; d++) rv[d] = sm[OFF_RT + lj * 9 + d];
#pragma unroll
            for (int u = 0; u < 8; u++) {
                const int h = h0 + u;
                float acc = sm[OFF_B1F + h];
#pragma unroll
                for (int d = 0; d < 9; d++) acc += rv[d] * sm[OFF_W1F + d * 32 + h];
                sm[OFF_H + lj * 36 + h] = fmaxf(acc, 0.f);
            }
        }
        __syncthreads();

        // ---- Phase B': fused RE = H@W2T and S1pre = H@W2P; S1 = relu(...) ----
        float re[4][4];
        {
            float aR[4][4], aS[4][4];
#pragma unroll
            for (int i = 0; i < 4; i++)
#pragma unroll
                for (int u = 0; u < 4; u++) { aR[i][u] = 0.f; aS[i][u] = 0.f; }
#pragma unroll 4
            for (int k = 0; k < 32; k++) {
                const float4 br = *(const float4*)&sm[OFF_W2T + k * 64 + c0];
                const float4 bs = *(const float4*)&sm[OFF_W2P + k * 64 + c0];
#pragma unroll
                for (int i = 0; i < 4; i++) {
                    const float a = sm[OFF_H + (jr * 4 + i) * 36 + k];
                    aR[i][0] += a * br.x; aR[i][1] += a * br.y;
                    aR[i][2] += a * br.z; aR[i][3] += a * br.w;
                    aS[i][0] += a * bs.x; aS[i][1] += a * bs.y;
                    aS[i][2] += a * bs.z; aS[i][3] += a * bs.w;
                }
            }
            const float4 bf = *(const float4*)&sm[OFF_B2F + c0];
            const float4 ba = *(const float4*)&sm[OFF_B1A + c0];
            const float4 qa = *(const float4*)&sm[OFF_QA + c0];
#pragma unroll
            for (int i = 0; i < 4; i++) {
                const int lj = jr * 4 + i;
                const int gj = j0 + lj;
                const float4 ka = *(const float4*)&g_proj[(b * TT + gj) * 128 + 64 + c0];
                re[i][0] = aR[i][0] + bf.x; re[i][1] = aR[i][1] + bf.y;
                re[i][2] = aR[i][2] + bf.z; re[i][3] = aR[i][3] + bf.w;
                *(float4*)&sm[OFF_S1 + lj * 68 + c0] = make_float4(
                    fmaxf(aS[i][0] + qa.x - ka.x + ba.x, 0.f),
                    fmaxf(aS[i][1] + qa.y - ka.y + ba.y, 0.f),
                    fmaxf(aS[i][2] + qa.z - ka.z + ba.z, 0.f),
                    fmaxf(aS[i][3] + qa.w - ka.w + ba.w, 0.f));
            }
        }
        __syncthreads();

        // ---- Phase D: Sim = S1 @ W2A + b2a ; online softmax accumulate ----
        {
            float acc[4][4];
#pragma unroll
            for (int i = 0; i < 4; i++)
#pragma unroll
                for (int u = 0; u < 4; u++) acc[i][u] = 0.f;
#pragma unroll 8
            for (int k = 0; k < 64; k++) {
                const float4 bv = *(const float4*)&sm[OFF_W2A + k * 64 + c0];
#pragma unroll
                for (int i = 0; i < 4; i++) {
                    const float a = sm[OFF_S1 + (jr * 4 + i) * 68 + k];
                    acc[i][0] += a * bv.x; acc[i][1] += a * bv.y;
                    acc[i][2] += a * bv.z; acc[i][3] += a * bv.w;
                }
            }
            const float4 bb = *(const float4*)&sm[OFF_B2A + c0];
#pragma unroll
            for (int i = 0; i < 4; i++) {
                const int gj = j0 + jr * 4 + i;
                const float4 vg = *(const float4*)&g_qkv[(b * TT + gj) * 192 + 128 + c0];
                float s[4]  = { acc[i][0] + bb.x, acc[i][1] + bb.y,
                                acc[i][2] + bb.z, acc[i][3] + bb.w };
                float vj[4] = { vg.x + re[i][0], vg.y + re[i][1],
                                vg.z + re[i][2], vg.w + re[i][3] };
#pragma unroll
                for (int u = 0; u < 4; u++) {
                    const float nm = fmaxf(m4[u], s[u]);
                    const float f = __expf(m4[u] - nm);
                    const float e = __expf(s[u] - nm);
                    l4[u] = l4[u] * f + e;
                    a4[u] = a4[u] * f + e * vj[u];
                    m4[u] = nm;
                }
            }
        }
    }

    // ---- cross-jr softmax combine: m->OFF_H, l->OFF_H+1024, a->OFF_S1 ----
    __syncthreads();
#pragma unroll
    for (int u = 0; u < 4; u++) {
        sm[OFF_H +         jr * 64 + c0 + u] = m4[u];
        sm[OFF_H + 1024 +  jr * 64 + c0 + u] = l4[u];
        sm[OFF_S1 +        jr * 64 + c0 + u] = a4[u];
    }
    __syncthreads();
    if (tid < 64) {
        float M = -1e30f;
#pragma unroll
        for (int p = 0; p < 16; p++) M = fmaxf(M, sm[OFF_H + p * 64 + tid]);
        float L = 0.f, A = 0.f;
#pragma unroll
        for (int p = 0; p < 16; p++) {
            const float f = __expf(sm[OFF_H + p * 64 + tid] - M);
            L += sm[OFF_H + 1024 + p * 64 + tid] * f;
            A += sm[OFF_S1 + p * 64 + tid] * f;
        }
        out[row * 64 + tid] = A / L;
    }
}

// ---------------------------------------------------------------------------
extern "C" void kernel_launch(void* const* d_in, const int* in_sizes, int n_in,
                              void* d_out, int out_size) {
    (void)in_sizes; (void)n_in; (void)out_size;
    const float* x      = (const float*)d_in[0];
    const float* r      = (const float*)d_in[1];
    const float* w_qkv  = (const float*)d_in[2];
    const float* tpr_w1 = (const float*)d_in[3];
    const float* tpr_b1 = (const float*)d_in[4];
    const float* bn_g   = (const float*)d_in[5];
    const float* bn_b   = (const float*)d_in[6];
    const float* bn_m   = (const float*)d_in[7];
    const float* bn_v   = (const float*)d_in[8];
    const float* tpr_w2 = (const float*)d_in[9];
    const float* tpr_b2 = (const float*)d_in[10];
    const float* aw1    = (const float*)d_in[11];
    const float* ab1    = (const float*)d_in[12];
    const float* aw2    = (const float*)d_in[13];
    const float* ab2    = (const float*)d_in[14];
    float* out = (float*)d_out;

    cudaFuncSetAttribute(va_kernel, cudaFuncAttributeMaxDynamicSharedMemorySize,
                         SMEM_BYTES);

    qkv_kernel<<<NROW, 192>>>(x, w_qkv);
    proj_kernel<<<NROW, 128>>>(aw1);
    w2p_kernel<<<1, 64>>>(tpr_w2, tpr_b2, aw1, ab1);
    va_kernel<<<NROW, 256, SMEM_BYTES>>>(r, tpr_w1, tpr_b1, bn_g, bn_b, bn_m, bn_v,
                                         tpr_w2, tpr_b2, aw2, ab2, out);
}

// round 4
// speedup vs baseline: 1.3754x; 1.0859x over previous
#include <cuda_runtime.h>
#include <cuda_bf16.h>
#include <math.h>
#include <stdint.h>

#define TT 256
#define NROW 2048            // B*T
#define BN_EPS 1e-5f

// scratch
__device__ float g_qkv[NROW * 192];    // q|k|v per row
__device__ float g_proj[NROW * 128];   // qA|kA per row  ({q,k}@attn_w1)
__device__ float g_w2p[32 * 64];       // tpr_w2 @ attn_w1
__device__ float g_b1a[64];            // tpr_b2 @ attn_w1 + attn_b1

// ---------------------------------------------------------------------------
// Kernel 1: qkv = x @ w_qkv
// ---------------------------------------------------------------------------
__global__ __launch_bounds__(192) void qkv_kernel(const float* __restrict__ x,
                                                  const float* __restrict__ w) {
    __shared__ float xs[128];
    const int row = blockIdx.x;
    const int tid = threadIdx.x;
    if (tid < 128) xs[tid] = x[row * 128 + tid];
    __syncthreads();
    float a0 = 0.f, a1 = 0.f, a2 = 0.f, a3 = 0.f;
#pragma unroll 8
    for (int d = 0; d < 128; d += 4) {
        a0 += xs[d + 0] * w[(d + 0) * 192 + tid];
        a1 += xs[d + 1] * w[(d + 1) * 192 + tid];
        a2 += xs[d + 2] * w[(d + 2) * 192 + tid];
        a3 += xs[d + 3] * w[(d + 3) * 192 + tid];
    }
    g_qkv[row * 192 + tid] = (a0 + a1) + (a2 + a3);
}

// ---------------------------------------------------------------------------
// Kernel 1b: qA = q@Aw1, kA = k@Aw1 per row
// ---------------------------------------------------------------------------
__global__ __launch_bounds__(128) void proj_kernel(const float* __restrict__ aw1) {
    __shared__ float qk[128];
    const int row = blockIdx.x;
    const int tid = threadIdx.x;
    qk[tid] = g_qkv[row * 192 + tid];
    __syncthreads();
    const float* src = (tid < 64) ? qk : (qk + 64);
    const int col = tid & 63;
    float a0 = 0.f, a1 = 0.f;
#pragma unroll 8
    for (int d = 0; d < 64; d += 2) {
        a0 += src[d + 0] * aw1[(d + 0) * 64 + col];
        a1 += src[d + 1] * aw1[(d + 1) * 64 + col];
    }
    g_proj[row * 128 + tid] = a0 + a1;
}

// ---------------------------------------------------------------------------
// Kernel 1c: W2P = tpr_w2 @ attn_w1; b1a = tpr_b2 @ attn_w1 + attn_b1
// ---------------------------------------------------------------------------
__global__ __launch_bounds__(64) void w2p_kernel(const float* __restrict__ tpr_w2,
                                                 const float* __restrict__ tpr_b2,
                                                 const float* __restrict__ aw1,
                                                 const float* __restrict__ ab1) {
    __shared__ float w2s[2048];
    __shared__ float a1s[4096];
    const int tid = threadIdx.x;
    for (int i = tid; i < 2048; i += 64) w2s[i] = tpr_w2[i];
    for (int i = tid; i < 4096; i += 64) a1s[i] = aw1[i];
    __syncthreads();
    const int c = tid;
    for (int h = 0; h < 32; h++) {
        float acc = 0.f;
#pragma unroll 8
        for (int d = 0; d < 64; d++) acc += w2s[h * 64 + d] * a1s[d * 64 + c];
        g_w2p[h * 64 + c] = acc;
    }
    float accb = ab1[c];
#pragma unroll 8
    for (int d = 0; d < 64; d++) accb += tpr_b2[d] * a1s[d * 64 + c];
    g_b1a[c] = accb;
}

// ---------------------------------------------------------------------------
// helpers
// ---------------------------------------------------------------------------
__device__ __forceinline__ void mma_bf16(float* d, const uint32_t* a,
                                         uint32_t b0, uint32_t b1) {
    asm volatile(
        "mma.sync.aligned.m16n8k16.row.col.f32.bf16.bf16.f32 "
        "{%0,%1,%2,%3}, {%4,%5,%6,%7}, {%8,%9}, {%0,%1,%2,%3};"
        : "+f"(d[0]), "+f"(d[1]), "+f"(d[2]), "+f"(d[3])
        : "r"(a[0]), "r"(a[1]), "r"(a[2]), "r"(a[3]), "r"(b0), "r"(b1));
}

__device__ __forceinline__ uint32_t b2u(__nv_bfloat162 v) {
    return *reinterpret_cast<uint32_t*>(&v);
}

// split (x,y) into bf16 hi-pair and lo-pair words (low 16 bits = first elem)
__device__ __forceinline__ void split2(float x, float y, uint32_t& hi, uint32_t& lo) {
    __nv_bfloat16 hx = __float2bfloat16_rn(x);
    __nv_bfloat16 hy = __float2bfloat16_rn(y);
    float rx = x - __bfloat162float(hx);
    float ry = y - __bfloat162float(hy);
    __nv_bfloat162 h2; h2.x = hx; h2.y = hy;
    hi = b2u(h2);
    lo = b2u(__floats2bfloat162_rn(rx, ry));
}

__device__ __forceinline__ uint32_t ld_u32(const __nv_bfloat16* p) {
    return *reinterpret_cast<const uint32_t*>(p);
}

// ---------------------------------------------------------------------------
// Shared memory byte offsets (all 16B-aligned)
// ---------------------------------------------------------------------------
#define SO_WPT_HI 0          // [128][40] bf16  (W' = [W2T|W2P]^T, k contiguous)
#define SO_WPT_LO 10240
#define SO_WAT_HI 20480      // [64][72] bf16   (W2A^T)
#define SO_WAT_LO 29696
#define SO_H_HI   38912      // [64][40] bf16
#define SO_H_LO   44032
#define SO_S1_HI  49152      // [64][72] bf16
#define SO_S1_LO  58368
#define SO_RE     67584      // [64][68] fp32  (also final-combine partials)
#define SO_SIM    84992      // [64][68] fp32  (aliased: KA tile, then Sim)
#define SO_RT     102400     // [64*9] fp32
#define SO_W1F    104704     // [9*32] fp32 (BN-folded)
#define SO_B1F    105856     // 32 fp32
#define SO_B2F    105984     // 64 fp32
#define SO_B1A    106240     // 64
#define SO_B2A    106496     // 64
#define SO_QA     106752     // 64
#define SMEM_BYTES 107008

__global__ __launch_bounds__(256, 2) void va_kernel(
    const float* __restrict__ r,
    const float* __restrict__ tpr_w1, const float* __restrict__ tpr_b1,
    const float* __restrict__ bn_g, const float* __restrict__ bn_b,
    const float* __restrict__ bn_m, const float* __restrict__ bn_v,
    const float* __restrict__ tpr_w2, const float* __restrict__ tpr_b2,
    const float* __restrict__ aw2, const float* __restrict__ ab2,
    float* __restrict__ out)
{
    extern __shared__ __align__(16) char sb[];
    __nv_bfloat16* WPT_HI = (__nv_bfloat16*)(sb + SO_WPT_HI);
    __nv_bfloat16* WPT_LO = (__nv_bfloat16*)(sb + SO_WPT_LO);
    __nv_bfloat16* WAT_HI = (__nv_bfloat16*)(sb + SO_WAT_HI);
    __nv_bfloat16* WAT_LO = (__nv_bfloat16*)(sb + SO_WAT_LO);
    __nv_bfloat16* H_HI   = (__nv_bfloat16*)(sb + SO_H_HI);
    __nv_bfloat16* H_LO   = (__nv_bfloat16*)(sb + SO_H_LO);
    __nv_bfloat16* S1_HI  = (__nv_bfloat16*)(sb + SO_S1_HI);
    __nv_bfloat16* S1_LO  = (__nv_bfloat16*)(sb + SO_S1_LO);
    float* REb  = (float*)(sb + SO_RE);
    float* SIMb = (float*)(sb + SO_SIM);
    float* RTb  = (float*)(sb + SO_RT);
    float* W1F  = (float*)(sb + SO_W1F);
    float* B1F  = (float*)(sb + SO_B1F);
    float* B2F  = (float*)(sb + SO_B2F);
    float* B1A  = (float*)(sb + SO_B1A);
    float* B2A  = (float*)(sb + SO_B2A);
    float* QA   = (float*)(sb + SO_QA);

    const int tid = threadIdx.x;
    const int row = blockIdx.x;          // b*T + i
    const int b = row >> 8;
    const int wid = tid >> 5, lane = tid & 31;
    const int gid = lane >> 2, tig = lane & 3;

    // ---- stage weights ----
    for (int idx = tid; idx < 288; idx += 256) {
        int ch = idx & 31;
        float sc = bn_g[ch] * rsqrtf(bn_v[ch] + BN_EPS);
        W1F[idx] = tpr_w1[idx] * sc;
    }
    if (tid < 32) {
        float sc = bn_g[tid] * rsqrtf(bn_v[tid] + BN_EPS);
        B1F[tid] = (tpr_b1[tid] - bn_m[tid]) * sc + bn_b[tid];
    }
    if (tid < 64) {
        B2F[tid] = tpr_b2[tid];
        B1A[tid] = g_b1a[tid];
        B2A[tid] = ab2[tid];
        QA[tid]  = g_proj[row * 128 + tid];
    }
    // W'^T = [W2T | W2P]^T : [128 n][32 k], hi/lo bf16
    for (int idx = tid; idx < 4096; idx += 256) {
        const int n = idx >> 5, k = idx & 31;
        const float v = (n < 64) ? tpr_w2[k * 64 + n] : g_w2p[k * 64 + (n - 64)];
        __nv_bfloat16 h = __float2bfloat16_rn(v);
        WPT_HI[n * 40 + k] = h;
        WPT_LO[n * 40 + k] = __float2bfloat16_rn(v - __bfloat162float(h));
    }
    // W2A^T : [64 n][64 k]
    for (int idx = tid; idx < 4096; idx += 256) {
        const int n = idx >> 6, k = idx & 63;
        const float v = aw2[k * 64 + n];
        __nv_bfloat16 h = __float2bfloat16_rn(v);
        WAT_HI[n * 72 + k] = h;
        WAT_LO[n * 72 + k] = __float2bfloat16_rn(v - __bfloat162float(h));
    }

    const int jr = tid >> 4;             // 0..15
    const int c0 = (tid & 15) << 2;      // 0..60

    float m4[4], l4[4], a4[4];
#pragma unroll
    for (int u = 0; u < 4; u++) { m4[u] = -1e30f; l4[u] = 0.f; a4[u] = 0.f; }

    const float* rrow = r + (size_t)row * (TT * 9);

    for (int jt = 0; jt < 4; jt++) {
        const int j0 = jt * 64;
        __syncthreads();   // prev-iter SIM/RE reads done; jt=0: weights staged
        // ---- stage r tile + KA tile (KA lives in SIM buffer) ----
        for (int idx = tid; idx < 576; idx += 256)
            RTb[idx] = rrow[j0 * 9 + idx];
        for (int idx = tid; idx < 4096; idx += 256) {
            const int j = idx >> 6, c = idx & 63;
            SIMb[j * 68 + c] = g_proj[(b * TT + j0 + j) * 128 + 64 + c];
        }
        __syncthreads();

        // ---- Phase A (SIMT): H = relu(r @ W1F + B1F), write bf16 hi/lo ----
        {
            const int lj = tid >> 2;
            const int h0 = (tid & 3) << 3;
            float rv[9];
#pragma unroll
            for (int d = 0; d < 9; d++) rv[d] = RTb[lj * 9 + d];
            float hv[8];
#pragma unroll
            for (int u = 0; u < 8; u++) {
                const int h = h0 + u;
                float acc = B1F[h];
#pragma unroll
                for (int d = 0; d < 9; d++) acc += rv[d] * W1F[d * 32 + h];
                hv[u] = fmaxf(acc, 0.f);
            }
#pragma unroll
            for (int p = 0; p < 4; p++) {
                uint32_t hi, lo;
                split2(hv[2 * p], hv[2 * p + 1], hi, lo);
                *(uint32_t*)(H_HI + lj * 40 + h0 + 2 * p) = hi;
                *(uint32_t*)(H_LO + lj * 40 + h0 + 2 * p) = lo;
            }
        }
        __syncthreads();

        // ---- Phase B' (MMA): [RE | S1pre] = H @ W'  (64 x 128) ----
        {
            const int m = wid & 3, sel = wid >> 2;
            const int r0 = m * 16 + gid;
            float acc[8][4];
#pragma unroll
            for (int t = 0; t < 8; t++)
#pragma unroll
                for (int u = 0; u < 4; u++) acc[t][u] = 0.f;
#pragma unroll
            for (int ks = 0; ks < 2; ks++) {
                const int kb = ks * 16 + 2 * tig;
                uint32_t ahi[4], alo[4];
                ahi[0] = ld_u32(H_HI + r0 * 40 + kb);
                ahi[1] = ld_u32(H_HI + (r0 + 8) * 40 + kb);
                ahi[2] = ld_u32(H_HI + r0 * 40 + kb + 8);
                ahi[3] = ld_u32(H_HI + (r0 + 8) * 40 + kb + 8);
                alo[0] = ld_u32(H_LO + r0 * 40 + kb);
                alo[1] = ld_u32(H_LO + (r0 + 8) * 40 + kb);
                alo[2] = ld_u32(H_LO + r0 * 40 + kb + 8);
                alo[3] = ld_u32(H_LO + (r0 + 8) * 40 + kb + 8);
#pragma unroll
                for (int t = 0; t < 8; t++) {
                    const int n = sel * 64 + t * 8 + gid;
                    const uint32_t bhi0 = ld_u32(WPT_HI + n * 40 + kb);
                    const uint32_t bhi1 = ld_u32(WPT_HI + n * 40 + kb + 8);
                    const uint32_t blo0 = ld_u32(WPT_LO + n * 40 + kb);
                    const uint32_t blo1 = ld_u32(WPT_LO + n * 40 + kb + 8);
                    mma_bf16(acc[t], ahi, bhi0, bhi1);
                    mma_bf16(acc[t], ahi, blo0, blo1);
                    mma_bf16(acc[t], alo, bhi0, bhi1);
                }
            }
            if (sel == 0) {        // RE epilogue
#pragma unroll
                for (int t = 0; t < 8; t++) {
                    const int c = t * 8 + 2 * tig;
                    const float2 bb = *(const float2*)(B2F + c);
                    *(float2*)(REb + r0 * 68 + c) =
                        make_float2(acc[t][0] + bb.x, acc[t][1] + bb.y);
                    *(float2*)(REb + (r0 + 8) * 68 + c) =
                        make_float2(acc[t][2] + bb.x, acc[t][3] + bb.y);
                }
            } else {               // S1 = relu(S1pre + qa - ka + b1a)
#pragma unroll
                for (int t = 0; t < 8; t++) {
                    const int c = t * 8 + 2 * tig;
                    const float2 qb = *(const float2*)(QA + c);
                    const float2 ba = *(const float2*)(B1A + c);
                    const float2 k0v = *(const float2*)(SIMb + r0 * 68 + c);
                    const float2 k1v = *(const float2*)(SIMb + (r0 + 8) * 68 + c);
                    const float s00 = fmaxf(acc[t][0] + qb.x - k0v.x + ba.x, 0.f);
                    const float s01 = fmaxf(acc[t][1] + qb.y - k0v.y + ba.y, 0.f);
                    const float s10 = fmaxf(acc[t][2] + qb.x - k1v.x + ba.x, 0.f);
                    const float s11 = fmaxf(acc[t][3] + qb.y - k1v.y + ba.y, 0.f);
                    uint32_t hi, lo;
                    split2(s00, s01, hi, lo);
                    *(uint32_t*)(S1_HI + r0 * 72 + c) = hi;
                    *(uint32_t*)(S1_LO + r0 * 72 + c) = lo;
                    split2(s10, s11, hi, lo);
                    *(uint32_t*)(S1_HI + (r0 + 8) * 72 + c) = hi;
                    *(uint32_t*)(S1_LO + (r0 + 8) * 72 + c) = lo;
                }
            }
        }
        __syncthreads();

        // ---- Phase D (MMA): Sim = S1 @ W2A  (64 x 64) ----
        {
            const int m = wid & 3, nq = wid >> 2;
            const int r0 = m * 16 + gid;
            float acc[4][4];
#pragma unroll
            for (int t = 0; t < 4; t++)
#pragma unroll
                for (int u = 0; u < 4; u++) acc[t][u] = 0.f;
#pragma unroll
            for (int ks = 0; ks < 4; ks++) {
                const int kb = ks * 16 + 2 * tig;
                uint32_t ahi[4], alo[4];
                ahi[0] = ld_u32(S1_HI + r0 * 72 + kb);
                ahi[1] = ld_u32(S1_HI + (r0 + 8) * 72 + kb);
                ahi[2] = ld_u32(S1_HI + r0 * 72 + kb + 8);
                ahi[3] = ld_u32(S1_HI + (r0 + 8) * 72 + kb + 8);
                alo[0] = ld_u32(S1_LO + r0 * 72 + kb);
                alo[1] = ld_u32(S1_LO + (r0 + 8) * 72 + kb);
                alo[2] = ld_u32(S1_LO + r0 * 72 + kb + 8);
                alo[3] = ld_u32(S1_LO + (r0 + 8) * 72 + kb + 8);
#pragma unroll
                for (int t = 0; t < 4; t++) {
                    const int n = nq * 32 + t * 8 + gid;
                    const uint32_t bhi0 = ld_u32(WAT_HI + n * 72 + kb);
                    const uint32_t bhi1 = ld_u32(WAT_HI + n * 72 + kb + 8);
                    const uint32_t blo0 = ld_u32(WAT_LO + n * 72 + kb);
                    const uint32_t blo1 = ld_u32(WAT_LO + n * 72 + kb + 8);
                    mma_bf16(acc[t], ahi, bhi0, bhi1);
                    mma_bf16(acc[t], ahi, blo0, blo1);
                    mma_bf16(acc[t], alo, bhi0, bhi1);
                }
            }
#pragma unroll
            for (int t = 0; t < 4; t++) {
                const int c = nq * 32 + t * 8 + 2 * tig;
                *(float2*)(SIMb + r0 * 68 + c) = make_float2(acc[t][0], acc[t][1]);
                *(float2*)(SIMb + (r0 + 8) * 68 + c) = make_float2(acc[t][2], acc[t][3]);
            }
        }
        __syncthreads();

        // ---- online softmax accumulate (SIMT) ----
        {
            const float4 bb = *(const float4*)(B2A + c0);
#pragma unroll
            for (int i = 0; i < 4; i++) {
                const int lj = jr * 4 + i;
                const int gj = j0 + lj;
                const float4 sv = *(const float4*)(SIMb + lj * 68 + c0);
                const float4 re = *(const float4*)(REb + lj * 68 + c0);
                const float4 vg = *(const float4*)&g_qkv[(b * TT + gj) * 192 + 128 + c0];
                float s[4]  = { sv.x + bb.x, sv.y + bb.y, sv.z + bb.z, sv.w + bb.w };
                float vj[4] = { vg.x + re.x, vg.y + re.y, vg.z + re.z, vg.w + re.w };
#pragma unroll
                for (int u = 0; u < 4; u++) {
                    const float nm = fmaxf(m4[u], s[u]);
                    const float f = __expf(m4[u] - nm);
                    const float e = __expf(s[u] - nm);
                    l4[u] = l4[u] * f + e;
                    a4[u] = a4[u] * f + e * vj[u];
                    m4[u] = nm;
                }
            }
        }
    }

    // ---- cross-jr softmax combine (partials in RE region) ----
    __syncthreads();
#pragma unroll
    for (int u = 0; u < 4; u++) {
        REb[jr * 64 + c0 + u]        = m4[u];
        REb[1024 + jr * 64 + c0 + u] = l4[u];
        REb[2048 + jr * 64 + c0 + u] = a4[u];
    }
    __syncthreads();
    if (tid < 64) {
        float M = -1e30f;
#pragma unroll
        for (int p = 0; p < 16; p++) M = fmaxf(M, REb[p * 64 + tid]);
        float L = 0.f, A = 0.f;
#pragma unroll
        for (int p = 0; p < 16; p++) {
            const float f = __expf(REb[p * 64 + tid] - M);
            L += REb[1024 + p * 64 + tid] * f;
            A += REb[2048 + p * 64 + tid] * f;
        }
        out[row * 64 + tid] = A / L;
    }
}

// ---------------------------------------------------------------------------
extern "C" void kernel_launch(void* const* d_in, const int* in_sizes, int n_in,
                              void* d_out, int out_size) {
    (void)in_sizes; (void)n_in; (void)out_size;
    const float* x      = (const float*)d_in[0];
    const float* r      = (const float*)d_in[1];
    const float* w_qkv  = (const float*)d_in[2];
    const float* tpr_w1 = (const float*)d_in[3];
    const float* tpr_b1 = (const float*)d_in[4];
    const float* bn_g   = (const float*)d_in[5];
    const float* bn_b   = (const float*)d_in[6];
    const float* bn_m   = (const float*)d_in[7];
    const float* bn_v   = (const float*)d_in[8];
    const float* tpr_w2 = (const float*)d_in[9];
    const float* tpr_b2 = (const float*)d_in[10];
    const float* aw1    = (const float*)d_in[11];
    const float* ab1    = (const float*)d_in[12];
    const float* aw2    = (const float*)d_in[13];
    const float* ab2    = (const float*)d_in[14];
    float* out = (float*)d_out;

    cudaFuncSetAttribute(va_kernel, cudaFuncAttributeMaxDynamicSharedMemorySize,
                         SMEM_BYTES);

    qkv_kernel<<<NROW, 192>>>(x, w_qkv);
    proj_kernel<<<NROW, 128>>>(aw1);
    w2p_kernel<<<1, 64>>>(tpr_w2, tpr_b2, aw1, ab1);
    va_kernel<<<NROW, 256, SMEM_BYTES>>>(r, tpr_w1, tpr_b1, bn_g, bn_b, bn_m, bn_v,
                                         tpr_w2, tpr_b2, aw2, ab2, out);
}

// round 5
// speedup vs baseline: 1.4483x; 1.0530x over previous
#include <cuda_runtime.h>
#include <cuda_bf16.h>
#include <math.h>
#include <stdint.h>

#define TT 256
#define NROW 2048            // B*T
#define BN_EPS 1e-5f

// scratch
__device__ float g_qkv[NROW * 192];    // q|k|v per row
__device__ float g_proj[NROW * 128];   // qA|kA per row  ({q,k}@attn_w1)
__device__ float g_w2p[32 * 64];       // tpr_w2 @ attn_w1
__device__ float g_b1a[64];            // tpr_b2 @ attn_w1 + attn_b1

// ---------------------------------------------------------------------------
// Kernel 1: qkv = x @ w_qkv
// ---------------------------------------------------------------------------
__global__ __launch_bounds__(192) void qkv_kernel(const float* __restrict__ x,
                                                  const float* __restrict__ w) {
    __shared__ float xs[128];
    const int row = blockIdx.x;
    const int tid = threadIdx.x;
    if (tid < 128) xs[tid] = x[row * 128 + tid];
    __syncthreads();
    float a0 = 0.f, a1 = 0.f, a2 = 0.f, a3 = 0.f;
#pragma unroll 8
    for (int d = 0; d < 128; d += 4) {
        a0 += xs[d + 0] * w[(d + 0) * 192 + tid];
        a1 += xs[d + 1] * w[(d + 1) * 192 + tid];
        a2 += xs[d + 2] * w[(d + 2) * 192 + tid];
        a3 += xs[d + 3] * w[(d + 3) * 192 + tid];
    }
    g_qkv[row * 192 + tid] = (a0 + a1) + (a2 + a3);
}

// ---------------------------------------------------------------------------
// Kernel 1b: qA = q@Aw1, kA = k@Aw1 per row
// ---------------------------------------------------------------------------
__global__ __launch_bounds__(128) void proj_kernel(const float* __restrict__ aw1) {
    __shared__ float qk[128];
    const int row = blockIdx.x;
    const int tid = threadIdx.x;
    qk[tid] = g_qkv[row * 192 + tid];
    __syncthreads();
    const float* src = (tid < 64) ? qk : (qk + 64);
    const int col = tid & 63;
    float a0 = 0.f, a1 = 0.f;
#pragma unroll 8
    for (int d = 0; d < 64; d += 2) {
        a0 += src[d + 0] * aw1[(d + 0) * 64 + col];
        a1 += src[d + 1] * aw1[(d + 1) * 64 + col];
    }
    g_proj[row * 128 + tid] = a0 + a1;
}

// ---------------------------------------------------------------------------
// Kernel 1c: W2P = tpr_w2 @ attn_w1; b1a = tpr_b2 @ attn_w1 + attn_b1
// ---------------------------------------------------------------------------
__global__ __launch_bounds__(64) void w2p_kernel(const float* __restrict__ tpr_w2,
                                                 const float* __restrict__ tpr_b2,
                                                 const float* __restrict__ aw1,
                                                 const float* __restrict__ ab1) {
    __shared__ float w2s[2048];
    __shared__ float a1s[4096];
    const int tid = threadIdx.x;
    for (int i = tid; i < 2048; i += 64) w2s[i] = tpr_w2[i];
    for (int i = tid; i < 4096; i += 64) a1s[i] = aw1[i];
    __syncthreads();
    const int c = tid;
    for (int h = 0; h < 32; h++) {
        float acc = 0.f;
#pragma unroll 8
        for (int d = 0; d < 64; d++) acc += w2s[h * 64 + d] * a1s[d * 64 + c];
        g_w2p[h * 64 + c] = acc;
    }
    float accb = ab1[c];
#pragma unroll 8
    for (int d = 0; d < 64; d++) accb += tpr_b2[d] * a1s[d * 64 + c];
    g_b1a[c] = accb;
}

// ---------------------------------------------------------------------------
// helpers
// ---------------------------------------------------------------------------
__device__ __forceinline__ void mma_bf16(float* d, const uint32_t* a,
                                         uint32_t b0, uint32_t b1) {
    asm volatile(
        "mma.sync.aligned.m16n8k16.row.col.f32.bf16.bf16.f32 "
        "{%0,%1,%2,%3}, {%4,%5,%6,%7}, {%8,%9}, {%0,%1,%2,%3};"
        : "+f"(d[0]), "+f"(d[1]), "+f"(d[2]), "+f"(d[3])
        : "r"(a[0]), "r"(a[1]), "r"(a[2]), "r"(a[3]), "r"(b0), "r"(b1));
}

__device__ __forceinline__ void ldsm_x4(uint32_t& r0, uint32_t& r1,
                                        uint32_t& r2, uint32_t& r3, uint32_t addr) {
    asm volatile("ldmatrix.sync.aligned.m8n8.x4.shared.b16 {%0,%1,%2,%3}, [%4];"
                 : "=r"(r0), "=r"(r1), "=r"(r2), "=r"(r3) : "r"(addr));
}

__device__ __forceinline__ uint32_t b2u(__nv_bfloat162 v) {
    return *reinterpret_cast<uint32_t*>(&v);
}

__device__ __forceinline__ void split2(float x, float y, uint32_t& hi, uint32_t& lo) {
    __nv_bfloat16 hx = __float2bfloat16_rn(x);
    __nv_bfloat16 hy = __float2bfloat16_rn(y);
    float rx = x - __bfloat162float(hx);
    float ry = y - __bfloat162float(hy);
    __nv_bfloat162 h2; h2.x = hx; h2.y = hy;
    hi = b2u(h2);
    lo = b2u(__floats2bfloat162_rn(rx, ry));
}

// ---------------------------------------------------------------------------
// Shared memory byte offsets (16B aligned). Strides: bf16 mats 40/72 elems.
// ---------------------------------------------------------------------------
#define SO_WRE_HI 0          // [64][40] bf16  W2T^T  (RE half)
#define SO_WRE_LO 5120
#define SO_WS1_HI 10240      // [64][40] bf16  W2P^T  (S1 half)
#define SO_WS1_LO 15360
#define SO_WAT_HI 20480      // [64][72] bf16  W2A^T
#define SO_WAT_LO 29696
#define SO_H_HI   38912      // [64][40] bf16
#define SO_H_LO   44032
#define SO_RE     49152      // [64][68] fp32  vj buffer (+ final-combine)
#define SO_SIM    66560      // [64][68] fp32  KA tile, then Sim
#define SO_RT     83968      // [64*9] fp32
#define SO_W1F    86272      // [9*32] fp32
#define SO_B1F    87424      // 32
#define SO_B2F    87552      // 64
#define SO_B1A    87808      // 64
#define SO_B2A    88064      // 64
#define SO_QA     88320      // 64
#define SMEM_BYTES 88576

__global__ __launch_bounds__(256, 2) void va_kernel(
    const float* __restrict__ r,
    const float* __restrict__ tpr_w1, const float* __restrict__ tpr_b1,
    const float* __restrict__ bn_g, const float* __restrict__ bn_b,
    const float* __restrict__ bn_m, const float* __restrict__ bn_v,
    const float* __restrict__ tpr_w2, const float* __restrict__ tpr_b2,
    const float* __restrict__ aw2, const float* __restrict__ ab2,
    float* __restrict__ out)
{
    extern __shared__ __align__(16) char sb[];
    __nv_bfloat16* WRE_HI = (__nv_bfloat16*)(sb + SO_WRE_HI);
    __nv_bfloat16* WRE_LO = (__nv_bfloat16*)(sb + SO_WRE_LO);
    __nv_bfloat16* WS1_HI = (__nv_bfloat16*)(sb + SO_WS1_HI);
    __nv_bfloat16* WS1_LO = (__nv_bfloat16*)(sb + SO_WS1_LO);
    __nv_bfloat16* WAT_HI = (__nv_bfloat16*)(sb + SO_WAT_HI);
    __nv_bfloat16* WAT_LO = (__nv_bfloat16*)(sb + SO_WAT_LO);
    __nv_bfloat16* H_HI   = (__nv_bfloat16*)(sb + SO_H_HI);
    __nv_bfloat16* H_LO   = (__nv_bfloat16*)(sb + SO_H_LO);
    float* REb  = (float*)(sb + SO_RE);
    float* SIMb = (float*)(sb + SO_SIM);
    float* RTb  = (float*)(sb + SO_RT);
    float* W1F  = (float*)(sb + SO_W1F);
    float* B1F  = (float*)(sb + SO_B1F);
    float* B2F  = (float*)(sb + SO_B2F);
    float* B1A  = (float*)(sb + SO_B1A);
    float* B2A  = (float*)(sb + SO_B2A);
    float* QA   = (float*)(sb + SO_QA);

    const int tid = threadIdx.x;
    const int row = blockIdx.x;          // b*T + i
    const int b = row >> 8;
    const int wid = tid >> 5, lane = tid & 31;
    const int gid = lane >> 2, tig = lane & 3;

    // ldmatrix per-lane address components
    const int arow = lane & 7, asel = lane >> 3;   // tile index within x4

    // ---- stage weights ----
    for (int idx = tid; idx < 288; idx += 256) {
        int ch = idx & 31;
        float sc = bn_g[ch] * rsqrtf(bn_v[ch] + BN_EPS);
        W1F[idx] = tpr_w1[idx] * sc;
    }
    if (tid < 32) {
        float sc = bn_g[tid] * rsqrtf(bn_v[tid] + BN_EPS);
        B1F[tid] = (tpr_b1[tid] - bn_m[tid]) * sc + bn_b[tid];
    }
    if (tid < 64) {
        B2F[tid] = tpr_b2[tid];
        B1A[tid] = g_b1a[tid];
        B2A[tid] = ab2[tid];
        QA[tid]  = g_proj[row * 128 + tid];
    }
    // W2T^T -> WRE, W2P^T -> WS1  ([64 n][32 k], stride 40)
    for (int idx = tid; idx < 2048; idx += 256) {
        const int n = idx >> 5, k = idx & 31;
        float v = tpr_w2[k * 64 + n];
        __nv_bfloat16 h = __float2bfloat16_rn(v);
        WRE_HI[n * 40 + k] = h;
        WRE_LO[n * 40 + k] = __float2bfloat16_rn(v - __bfloat162float(h));
        v = g_w2p[k * 64 + n];
        h = __float2bfloat16_rn(v);
        WS1_HI[n * 40 + k] = h;
        WS1_LO[n * 40 + k] = __float2bfloat16_rn(v - __bfloat162float(h));
    }
    // W2A^T : [64 n][64 k], stride 72
    for (int idx = tid; idx < 4096; idx += 256) {
        const int n = idx >> 6, k = idx & 63;
        const float v = aw2[k * 64 + n];
        __nv_bfloat16 h = __float2bfloat16_rn(v);
        WAT_HI[n * 72 + k] = h;
        WAT_LO[n * 72 + k] = __float2bfloat16_rn(v - __bfloat162float(h));
    }

    const int jr = tid >> 4;             // 0..15
    const int c0 = (tid & 15) << 2;      // 0..60

    float m4[4], l4[4], a4[4];
#pragma unroll
    for (int u = 0; u < 4; u++) { m4[u] = -1e30f; l4[u] = 0.f; a4[u] = 0.f; }

    const float* rrow = r + (size_t)row * (TT * 9);

    // per-lane ldmatrix element-offsets
    const int wmod = wid & 3;
    const int m0 = wmod * 16;
    const int aoff = (m0 + arow + (asel & 1) * 8) * 40 + (asel >> 1) * 8;  // A (H, stride 40)
    const int brow = arow + (asel >> 1) * 8;                               // B row pattern
    const int bcol = (asel & 1) * 8;

    const uint32_t Hhi_a = (uint32_t)__cvta_generic_to_shared(H_HI);
    const uint32_t Hlo_a = (uint32_t)__cvta_generic_to_shared(H_LO);
    const uint32_t WS1hi_a = (uint32_t)__cvta_generic_to_shared(WS1_HI);
    const uint32_t WS1lo_a = (uint32_t)__cvta_generic_to_shared(WS1_LO);
    const uint32_t WREhi_a = (uint32_t)__cvta_generic_to_shared(WRE_HI);
    const uint32_t WRElo_a = (uint32_t)__cvta_generic_to_shared(WRE_LO);
    const uint32_t WAThi_a = (uint32_t)__cvta_generic_to_shared(WAT_HI);
    const uint32_t WATlo_a = (uint32_t)__cvta_generic_to_shared(WAT_LO);

    for (int jt = 0; jt < 4; jt++) {
        const int j0 = jt * 64;
        __syncthreads();   // prev-iter SIM/RE reads done; jt=0: weights staged
        // ---- stage r tile + KA tile (KA in SIM buffer) ----
        for (int idx = tid; idx < 576; idx += 256)
            RTb[idx] = rrow[j0 * 9 + idx];
        for (int idx = tid; idx < 4096; idx += 256) {
            const int j = idx >> 6, c = idx & 63;
            SIMb[j * 68 + c] = g_proj[(b * TT + j0 + j) * 128 + 64 + c];
        }
        __syncthreads();

        // ---- Phase A (SIMT): H = relu(r @ W1F + B1F) -> bf16 hi/lo ----
        {
            const int lj = tid >> 2;
            const int h0 = (tid & 3) << 3;
            float rv[9];
#pragma unroll
            for (int d = 0; d < 9; d++) rv[d] = RTb[lj * 9 + d];
            float hv[8];
#pragma unroll
            for (int u = 0; u < 8; u++) {
                const int h = h0 + u;
                float acc = B1F[h];
#pragma unroll
                for (int d = 0; d < 9; d++) acc += rv[d] * W1F[d * 32 + h];
                hv[u] = fmaxf(acc, 0.f);
            }
#pragma unroll
            for (int p = 0; p < 4; p++) {
                uint32_t hi, lo;
                split2(hv[2 * p], hv[2 * p + 1], hi, lo);
                *(uint32_t*)(H_HI + lj * 40 + h0 + 2 * p) = hi;
                *(uint32_t*)(H_LO + lj * 40 + h0 + 2 * p) = lo;
            }
        }
        __syncthreads();

        // ---- A fragments of H (both warp groups) ----
        uint32_t ahi[2][4], alo[2][4];
#pragma unroll
        for (int ks = 0; ks < 2; ks++) {
            ldsm_x4(ahi[ks][0], ahi[ks][1], ahi[ks][2], ahi[ks][3],
                    Hhi_a + (uint32_t)(aoff + ks * 16) * 2u);
            ldsm_x4(alo[ks][0], alo[ks][1], alo[ks][2], alo[ks][3],
                    Hlo_a + (uint32_t)(aoff + ks * 16) * 2u);
        }

        if (wid < 4) {
            // ======== warps 0-3: S1 (chained) then Sim ========
            float accS[8][4];
#pragma unroll
            for (int t = 0; t < 8; t++)
#pragma unroll
                for (int u = 0; u < 4; u++) accS[t][u] = 0.f;
#pragma unroll
            for (int nb = 0; nb < 8; nb += 2) {
#pragma unroll
                for (int ks = 0; ks < 2; ks++) {
                    const uint32_t off =
                        (uint32_t)((nb * 8 + brow) * 40 + ks * 16 + bcol) * 2u;
                    uint32_t h0, h1, h2, h3, l0, l1, l2, l3;
                    ldsm_x4(h0, h1, h2, h3, WS1hi_a + off);
                    ldsm_x4(l0, l1, l2, l3, WS1lo_a + off);
                    mma_bf16(accS[nb],     ahi[ks], h0, h1);
                    mma_bf16(accS[nb],     ahi[ks], l0, l1);
                    mma_bf16(accS[nb],     alo[ks], h0, h1);
                    mma_bf16(accS[nb + 1], ahi[ks], h2, h3);
                    mma_bf16(accS[nb + 1], ahi[ks], l2, l3);
                    mma_bf16(accS[nb + 1], alo[ks], h2, h3);
                }
            }
            // epilogue: S1 = relu(accS + qa - ka + b1a), repack to A-frags
            const int r0 = m0 + gid;
            uint32_t s1hi[4][4], s1lo[4][4];
#pragma unroll
            for (int kg = 0; kg < 4; kg++) {
#pragma unroll
                for (int half = 0; half < 2; half++) {
                    const int tt = 2 * kg + half;
                    const int c = tt * 8 + 2 * tig;
                    const float2 qa2 = *(const float2*)(QA + c);
                    const float2 ba2 = *(const float2*)(B1A + c);
                    const float2 ka0 = *(const float2*)(SIMb + r0 * 68 + c);
                    const float2 ka1 = *(const float2*)(SIMb + (r0 + 8) * 68 + c);
                    const float s00 = fmaxf(accS[tt][0] + qa2.x - ka0.x + ba2.x, 0.f);
                    const float s01 = fmaxf(accS[tt][1] + qa2.y - ka0.y + ba2.y, 0.f);
                    const float s10 = fmaxf(accS[tt][2] + qa2.x - ka1.x + ba2.x, 0.f);
                    const float s11 = fmaxf(accS[tt][3] + qa2.y - ka1.y + ba2.y, 0.f);
                    split2(s00, s01, s1hi[kg][half * 2], s1lo[kg][half * 2]);
                    split2(s10, s11, s1hi[kg][half * 2 + 1], s1lo[kg][half * 2 + 1]);
                }
            }
            // Sim = S1 @ W2A
            float accD[8][4];
#pragma unroll
            for (int t = 0; t < 8; t++)
#pragma unroll
                for (int u = 0; u < 4; u++) accD[t][u] = 0.f;
#pragma unroll
            for (int nb = 0; nb < 8; nb += 2) {
#pragma unroll
                for (int ks = 0; ks < 4; ks++) {
                    const uint32_t off =
                        (uint32_t)((nb * 8 + brow) * 72 + ks * 16 + bcol) * 2u;
                    uint32_t h0, h1, h2, h3, l0, l1, l2, l3;
                    ldsm_x4(h0, h1, h2, h3, WAThi_a + off);
                    ldsm_x4(l0, l1, l2, l3, WATlo_a + off);
                    mma_bf16(accD[nb],     s1hi[ks], h0, h1);
                    mma_bf16(accD[nb],     s1hi[ks], l0, l1);
                    mma_bf16(accD[nb],     s1lo[ks], h0, h1);
                    mma_bf16(accD[nb + 1], s1hi[ks], h2, h3);
                    mma_bf16(accD[nb + 1], s1hi[ks], l2, l3);
                    mma_bf16(accD[nb + 1], s1lo[ks], h2, h3);
                }
            }
#pragma unroll
            for (int tt = 0; tt < 8; tt++) {
                const int c = tt * 8 + 2 * tig;
                *(float2*)(SIMb + r0 * 68 + c) = make_float2(accD[tt][0], accD[tt][1]);
                *(float2*)(SIMb + (r0 + 8) * 68 + c) = make_float2(accD[tt][2], accD[tt][3]);
            }
        } else {
            // ======== warps 4-7: RE, fuse vg -> vj ========
            float accR[8][4];
#pragma unroll
            for (int t = 0; t < 8; t++)
#pragma unroll
                for (int u = 0; u < 4; u++) accR[t][u] = 0.f;
#pragma unroll
            for (int nb = 0; nb < 8; nb += 2) {
#pragma unroll
                for (int ks = 0; ks < 2; ks++) {
                    const uint32_t off =
                        (uint32_t)((nb * 8 + brow) * 40 + ks * 16 + bcol) * 2u;
                    uint32_t h0, h1, h2, h3, l0, l1, l2, l3;
                    ldsm_x4(h0, h1, h2, h3, WREhi_a + off);
                    ldsm_x4(l0, l1, l2, l3, WRElo_a + off);
                    mma_bf16(accR[nb],     ahi[ks], h0, h1);
                    mma_bf16(accR[nb],     ahi[ks], l0, l1);
                    mma_bf16(accR[nb],     alo[ks], h0, h1);
                    mma_bf16(accR[nb + 1], ahi[ks], h2, h3);
                    mma_bf16(accR[nb + 1], ahi[ks], l2, l3);
                    mma_bf16(accR[nb + 1], alo[ks], h2, h3);
                }
            }
            const int r0 = m0 + gid;
            const float* v0p = &g_qkv[(b * TT + j0 + r0) * 192 + 128];
            const float* v1p = &g_qkv[(b * TT + j0 + r0 + 8) * 192 + 128];
#pragma unroll
            for (int tt = 0; tt < 8; tt++) {
                const int c = tt * 8 + 2 * tig;
                const float2 bf2 = *(const float2*)(B2F + c);
                const float2 vg0 = *(const float2*)(v0p + c);
                const float2 vg1 = *(const float2*)(v1p + c);
                *(float2*)(REb + r0 * 68 + c) =
                    make_float2(accR[tt][0] + bf2.x + vg0.x, accR[tt][1] + bf2.y + vg0.y);
                *(float2*)(REb + (r0 + 8) * 68 + c) =
                    make_float2(accR[tt][2] + bf2.x + vg1.x, accR[tt][3] + bf2.y + vg1.y);
            }
        }
        __syncthreads();

        // ---- online softmax accumulate (SIMT, all threads) ----
        {
            const float4 bb = *(const float4*)(B2A + c0);
#pragma unroll
            for (int i = 0; i < 4; i++) {
                const int lj = jr * 4 + i;
                const float4 sv = *(const float4*)(SIMb + lj * 68 + c0);
                const float4 vj4 = *(const float4*)(REb + lj * 68 + c0);
                float s[4]  = { sv.x + bb.x, sv.y + bb.y, sv.z + bb.z, sv.w + bb.w };
                float vj[4] = { vj4.x, vj4.y, vj4.z, vj4.w };
#pragma unroll
                for (int u = 0; u < 4; u++) {
                    const float nm = fmaxf(m4[u], s[u]);
                    const float f = __expf(m4[u] - nm);
                    const float e = __expf(s[u] - nm);
                    l4[u] = l4[u] * f + e;
                    a4[u] = a4[u] * f + e * vj[u];
                    m4[u] = nm;
                }
            }
        }
    }

    // ---- cross-jr softmax combine (partials in RE region) ----
    __syncthreads();
#pragma unroll
    for (int u = 0; u < 4; u++) {
        REb[jr * 64 + c0 + u]        = m4[u];
        REb[1024 + jr * 64 + c0 + u] = l4[u];
        REb[2048 + jr * 64 + c0 + u] = a4[u];
    }
    __syncthreads();
    if (tid < 64) {
        float M = -1e30f;
#pragma unroll
        for (int p = 0; p < 16; p++) M = fmaxf(M, REb[p * 64 + tid]);
        float L = 0.f, A = 0.f;
#pragma unroll
        for (int p = 0; p < 16; p++) {
            const float f = __expf(REb[p * 64 + tid] - M);
            L += REb[1024 + p * 64 + tid] * f;
            A += REb[2048 + p * 64 + tid] * f;
        }
        out[row * 64 + tid] = A / L;
    }
}

// ---------------------------------------------------------------------------
extern "C" void kernel_launch(void* const* d_in, const int* in_sizes, int n_in,
                              void* d_out, int out_size) {
    (void)in_sizes; (void)n_in; (void)out_size;
    const float* x      = (const float*)d_in[0];
    const float* r      = (const float*)d_in[1];
    const float* w_qkv  = (const float*)d_in[2];
    const float* tpr_w1 = (const float*)d_in[3];
    const float* tpr_b1 = (const float*)d_in[4];
    const float* bn_g   = (const float*)d_in[5];
    const float* bn_b   = (const float*)d_in[6];
    const float* bn_m   = (const float*)d_in[7];
    const float* bn_v   = (const float*)d_in[8];
    const float* tpr_w2 = (const float*)d_in[9];
    const float* tpr_b2 = (const float*)d_in[10];
    const float* aw1    = (const float*)d_in[11];
    const float* ab1    = (const float*)d_in[12];
    const float* aw2    = (const float*)d_in[13];
    const float* ab2    = (const float*)d_in[14];
    float* out = (float*)d_out;

    cudaFuncSetAttribute(va_kernel, cudaFuncAttributeMaxDynamicSharedMemorySize,
                         SMEM_BYTES);

    qkv_kernel<<<NROW, 192>>>(x, w_qkv);
    proj_kernel<<<NROW, 128>>>(aw1);
    w2p_kernel<<<1, 64>>>(tpr_w2, tpr_b2, aw1, ab1);
    va_kernel<<<NROW, 256, SMEM_BYTES>>>(r, tpr_w1, tpr_b1, bn_g, bn_b, bn_m, bn_v,
                                         tpr_w2, tpr_b2, aw2, ab2, out);
}

// round 6
// speedup vs baseline: 1.4939x; 1.0314x over previous
#include <cuda_runtime.h>
#include <cuda_bf16.h>
#include <math.h>
#include <stdint.h>

#define TT 256
#define NROW 2048            // B*T
#define BN_EPS 1e-5f

// scratch
__device__ float g_qkv[NROW * 192];    // q|k|v per row
__device__ float g_proj[NROW * 128];   // qA|kA per row  ({q,k}@attn_w1)
__device__ float g_w2p[32 * 64];       // tpr_w2 @ attn_w1
__device__ float g_b1a[64];            // tpr_b2 @ attn_w1 + attn_b1

// ---------------------------------------------------------------------------
// Kernel 1: qkv = x @ w_qkv
// ---------------------------------------------------------------------------
__global__ __launch_bounds__(192) void qkv_kernel(const float* __restrict__ x,
                                                  const float* __restrict__ w) {
    __shared__ float xs[128];
    const int row = blockIdx.x;
    const int tid = threadIdx.x;
    if (tid < 128) xs[tid] = x[row * 128 + tid];
    __syncthreads();
    float a0 = 0.f, a1 = 0.f, a2 = 0.f, a3 = 0.f;
#pragma unroll 8
    for (int d = 0; d < 128; d += 4) {
        a0 += xs[d + 0] * w[(d + 0) * 192 + tid];
        a1 += xs[d + 1] * w[(d + 1) * 192 + tid];
        a2 += xs[d + 2] * w[(d + 2) * 192 + tid];
        a3 += xs[d + 3] * w[(d + 3) * 192 + tid];
    }
    g_qkv[row * 192 + tid] = (a0 + a1) + (a2 + a3);
}

// ---------------------------------------------------------------------------
// Kernel 1b: qA = q@Aw1, kA = k@Aw1 per row
// ---------------------------------------------------------------------------
__global__ __launch_bounds__(128) void proj_kernel(const float* __restrict__ aw1) {
    __shared__ float qk[128];
    const int row = blockIdx.x;
    const int tid = threadIdx.x;
    qk[tid] = g_qkv[row * 192 + tid];
    __syncthreads();
    const float* src = (tid < 64) ? qk : (qk + 64);
    const int col = tid & 63;
    float a0 = 0.f, a1 = 0.f;
#pragma unroll 8
    for (int d = 0; d < 64; d += 2) {
        a0 += src[d + 0] * aw1[(d + 0) * 64 + col];
        a1 += src[d + 1] * aw1[(d + 1) * 64 + col];
    }
    g_proj[row * 128 + tid] = a0 + a1;
}

// ---------------------------------------------------------------------------
// Kernel 1c: W2P = tpr_w2 @ attn_w1; b1a = tpr_b2 @ attn_w1 + attn_b1
// ---------------------------------------------------------------------------
__global__ __launch_bounds__(64) void w2p_kernel(const float* __restrict__ tpr_w2,
                                                 const float* __restrict__ tpr_b2,
                                                 const float* __restrict__ aw1,
                                                 const float* __restrict__ ab1) {
    __shared__ float w2s[2048];
    __shared__ float a1s[4096];
    const int tid = threadIdx.x;
    for (int i = tid; i < 2048; i += 64) w2s[i] = tpr_w2[i];
    for (int i = tid; i < 4096; i += 64) a1s[i] = aw1[i];
    __syncthreads();
    const int c = tid;
    for (int h = 0; h < 32; h++) {
        float acc = 0.f;
#pragma unroll 8
        for (int d = 0; d < 64; d++) acc += w2s[h * 64 + d] * a1s[d * 64 + c];
        g_w2p[h * 64 + c] = acc;
    }
    float accb = ab1[c];
#pragma unroll 8
    for (int d = 0; d < 64; d++) accb += tpr_b2[d] * a1s[d * 64 + c];
    g_b1a[c] = accb;
}

// ---------------------------------------------------------------------------
// helpers
// ---------------------------------------------------------------------------
__device__ __forceinline__ void mma_bf16(float* d, const uint32_t* a,
                                         uint32_t b0, uint32_t b1) {
    asm volatile(
        "mma.sync.aligned.m16n8k16.row.col.f32.bf16.bf16.f32 "
        "{%0,%1,%2,%3}, {%4,%5,%6,%7}, {%8,%9}, {%0,%1,%2,%3};"
        : "+f"(d[0]), "+f"(d[1]), "+f"(d[2]), "+f"(d[3])
        : "r"(a[0]), "r"(a[1]), "r"(a[2]), "r"(a[3]), "r"(b0), "r"(b1));
}

__device__ __forceinline__ void ldsm_x4(uint32_t& r0, uint32_t& r1,
                                        uint32_t& r2, uint32_t& r3, uint32_t addr) {
    asm volatile("ldmatrix.sync.aligned.m8n8.x4.shared.b16 {%0,%1,%2,%3}, [%4];"
                 : "=r"(r0), "=r"(r1), "=r"(r2), "=r"(r3) : "r"(addr));
}

__device__ __forceinline__ uint32_t b2u(__nv_bfloat162 v) {
    return *reinterpret_cast<uint32_t*>(&v);
}

__device__ __forceinline__ void split2(float x, float y, uint32_t& hi, uint32_t& lo) {
    __nv_bfloat16 hx = __float2bfloat16_rn(x);
    __nv_bfloat16 hy = __float2bfloat16_rn(y);
    float rx = x - __bfloat162float(hx);
    float ry = y - __bfloat162float(hy);
    __nv_bfloat162 h2; h2.x = hx; h2.y = hy;
    hi = b2u(h2);
    lo = b2u(__floats2bfloat162_rn(rx, ry));
}

__device__ __forceinline__ void split1(float x, __nv_bfloat16& hi, __nv_bfloat16& lo) {
    hi = __float2bfloat16_rn(x);
    lo = __float2bfloat16_rn(x - __bfloat162float(hi));
}

// One 4-n-tile 3-term group: 12 MMAs at dependency distance 4.
// Wbase: element offset (bf16 units) of B panel row 0; tiles t0..t0+3.
#define MMA_GROUP4(ACC, T0, AH, AL, WHI, WLO, STRIDE, KOFF)                       \
    do {                                                                          \
        uint32_t bh[8], bl[8];                                                    \
        ldsm_x4(bh[0], bh[1], bh[2], bh[3],                                       \
                WHI + (uint32_t)((((T0) * 8 + brow) * (STRIDE)) + (KOFF) + bcol) * 2u); \
        ldsm_x4(bh[4], bh[5], bh[6], bh[7],                                       \
                WHI + (uint32_t)(((((T0) + 2) * 8 + brow) * (STRIDE)) + (KOFF) + bcol) * 2u); \
        ldsm_x4(bl[0], bl[1], bl[2], bl[3],                                       \
                WLO + (uint32_t)((((T0) * 8 + brow) * (STRIDE)) + (KOFF) + bcol) * 2u); \
        ldsm_x4(bl[4], bl[5], bl[6], bl[7],                                       \
                WLO + (uint32_t)(((((T0) + 2) * 8 + brow) * (STRIDE)) + (KOFF) + bcol) * 2u); \
        mma_bf16(ACC[(T0) + 0], AH, bh[0], bh[1]);                                \
        mma_bf16(ACC[(T0) + 1], AH, bh[2], bh[3]);                                \
        mma_bf16(ACC[(T0) + 2], AH, bh[4], bh[5]);                                \
        mma_bf16(ACC[(T0) + 3], AH, bh[6], bh[7]);                                \
        mma_bf16(ACC[(T0) + 0], AH, bl[0], bl[1]);                                \
        mma_bf16(ACC[(T0) + 1], AH, bl[2], bl[3]);                                \
        mma_bf16(ACC[(T0) + 2], AH, bl[4], bl[5]);                                \
        mma_bf16(ACC[(T0) + 3], AH, bl[6], bl[7]);                                \
        mma_bf16(ACC[(T0) + 0], AL, bh[0], bh[1]);                                \
        mma_bf16(ACC[(T0) + 1], AL, bh[2], bh[3]);                                \
        mma_bf16(ACC[(T0) + 2], AL, bh[4], bh[5]);                                \
        mma_bf16(ACC[(T0) + 3], AL, bh[6], bh[7]);                                \
    } while (0)

// ---------------------------------------------------------------------------
// Shared memory byte offsets (16B aligned).
// strides (elems): W'/H 40, WAT 80, RT/W1FT 24, fp32 bufs 68
// ---------------------------------------------------------------------------
#define SO_WRE_HI 0          // [64][40] bf16  W2T^T
#define SO_WRE_LO 5120
#define SO_WS1_HI 10240      // [64][40] bf16  W2P^T
#define SO_WS1_LO 15360
#define SO_WAT_HI 20480      // [64][80] bf16  W2A^T
#define SO_WAT_LO 30720
#define SO_H_HI   40960      // [64][40] bf16
#define SO_H_LO   46080
#define SO_RT_HI  51200      // [64][24] bf16 (r tile, k padded to 16)
#define SO_RT_LO  54272
#define SO_W1T_HI 57344      // [32][24] bf16 (BN-folded W1^T)
#define SO_W1T_LO 58880
#define SO_RE     60416      // [64][68] fp32  vj buffer (+ final combine)
#define SO_SIM    77824      // [64][68] fp32  Sim
#define SO_B1F    95232      // 32 fp32
#define SO_B2F    95360      // 64
#define SO_B1A    95616      // 64
#define SO_B2A    95872      // 64
#define SO_QA     96128      // 64
#define SMEM_BYTES 96384

__global__ __launch_bounds__(256, 2) void va_kernel(
    const float* __restrict__ r,
    const float* __restrict__ tpr_w1, const float* __restrict__ tpr_b1,
    const float* __restrict__ bn_g, const float* __restrict__ bn_b,
    const float* __restrict__ bn_m, const float* __restrict__ bn_v,
    const float* __restrict__ tpr_w2, const float* __restrict__ tpr_b2,
    const float* __restrict__ aw2, const float* __restrict__ ab2,
    float* __restrict__ out)
{
    extern __shared__ __align__(16) char sb[];
    __nv_bfloat16* WRE_HI = (__nv_bfloat16*)(sb + SO_WRE_HI);
    __nv_bfloat16* WRE_LO = (__nv_bfloat16*)(sb + SO_WRE_LO);
    __nv_bfloat16* WS1_HI = (__nv_bfloat16*)(sb + SO_WS1_HI);
    __nv_bfloat16* WS1_LO = (__nv_bfloat16*)(sb + SO_WS1_LO);
    __nv_bfloat16* WAT_HI = (__nv_bfloat16*)(sb + SO_WAT_HI);
    __nv_bfloat16* WAT_LO = (__nv_bfloat16*)(sb + SO_WAT_LO);
    __nv_bfloat16* H_HI   = (__nv_bfloat16*)(sb + SO_H_HI);
    __nv_bfloat16* H_LO   = (__nv_bfloat16*)(sb + SO_H_LO);
    __nv_bfloat16* RT_HI  = (__nv_bfloat16*)(sb + SO_RT_HI);
    __nv_bfloat16* RT_LO  = (__nv_bfloat16*)(sb + SO_RT_LO);
    __nv_bfloat16* W1T_HI = (__nv_bfloat16*)(sb + SO_W1T_HI);
    __nv_bfloat16* W1T_LO = (__nv_bfloat16*)(sb + SO_W1T_LO);
    float* REb  = (float*)(sb + SO_RE);
    float* SIMb = (float*)(sb + SO_SIM);
    float* B1F  = (float*)(sb + SO_B1F);
    float* B2F  = (float*)(sb + SO_B2F);
    float* B1A  = (float*)(sb + SO_B1A);
    float* B2A  = (float*)(sb + SO_B2A);
    float* QA   = (float*)(sb + SO_QA);

    const int tid = threadIdx.x;
    const int row = blockIdx.x;          // b*T + i
    const int b = row >> 8;
    const int wid = tid >> 5, lane = tid & 31;
    const int gid = lane >> 2, tig = lane & 3;
    const int arow = lane & 7, asel = lane >> 3;

    // ---- stage weights (once) ----
    // zero padded k regions of RT / W1FT
    for (int idx = tid; idx < 64 * 24; idx += 256) { RT_HI[idx] = __nv_bfloat16(0.f); RT_LO[idx] = __nv_bfloat16(0.f); }
    for (int idx = tid; idx < 32 * 24; idx += 256) { W1T_HI[idx] = __nv_bfloat16(0.f); W1T_LO[idx] = __nv_bfloat16(0.f); }
    if (tid < 32) {
        float sc = bn_g[tid] * rsqrtf(bn_v[tid] + BN_EPS);
        B1F[tid] = (tpr_b1[tid] - bn_m[tid]) * sc + bn_b[tid];
    }
    if (tid < 64) {
        B2F[tid] = tpr_b2[tid];
        B1A[tid] = g_b1a[tid];
        B2A[tid] = ab2[tid];
        QA[tid]  = g_proj[row * 128 + tid];
    }
    __syncthreads();   // zero-fill visible before partial overwrite below (same warps though; keep for safety)
    for (int idx = tid; idx < 288; idx += 256) {      // W1FT (BN-folded, transposed)
        const int d = idx >> 5, n = idx & 31;
        const float sc = bn_g[n] * rsqrtf(bn_v[n] + BN_EPS);
        __nv_bfloat16 hi, lo;
        split1(tpr_w1[idx] * sc, hi, lo);
        W1T_HI[n * 24 + d] = hi;
        W1T_LO[n * 24 + d] = lo;
    }
    for (int idx = tid; idx < 2048; idx += 256) {     // W2T^T, W2P^T (stride 40)
        const int n = idx >> 5, k = idx & 31;
        __nv_bfloat16 hi, lo;
        split1(tpr_w2[k * 64 + n], hi, lo);
        WRE_HI[n * 40 + k] = hi; WRE_LO[n * 40 + k] = lo;
        split1(g_w2p[k * 64 + n], hi, lo);
        WS1_HI[n * 40 + k] = hi; WS1_LO[n * 40 + k] = lo;
    }
    for (int idx = tid; idx < 4096; idx += 256) {     // W2A^T (stride 80)
        const int n = idx >> 6, k = idx & 63;
        __nv_bfloat16 hi, lo;
        split1(aw2[k * 64 + n], hi, lo);
        WAT_HI[n * 80 + k] = hi; WAT_LO[n * 80 + k] = lo;
    }

    const int jr = tid >> 4;             // 0..15
    const int c0 = (tid & 15) << 2;      // 0..60

    float m4[4], l4[4], a4[4];
#pragma unroll
    for (int u = 0; u < 4; u++) { m4[u] = -1e30f; l4[u] = 0.f; a4[u] = 0.f; }

    const float* rrow = r + (size_t)row * (TT * 9);

    const int wmod = wid & 3;
    const int m0 = wmod * 16;
    const int brow = arow + (asel >> 1) * 8;
    const int bcol = (asel & 1) * 8;
    const int aoff40 = (m0 + arow + (asel & 1) * 8) * 40 + (asel >> 1) * 8;
    const int aoff24 = (m0 + arow + (asel & 1) * 8) * 24 + (asel >> 1) * 8;

    const uint32_t Hhi_a   = (uint32_t)__cvta_generic_to_shared(H_HI);
    const uint32_t Hlo_a   = (uint32_t)__cvta_generic_to_shared(H_LO);
    const uint32_t RThi_a  = (uint32_t)__cvta_generic_to_shared(RT_HI);
    const uint32_t RTlo_a  = (uint32_t)__cvta_generic_to_shared(RT_LO);
    const uint32_t W1Thi_a = (uint32_t)__cvta_generic_to_shared(W1T_HI);
    const uint32_t W1Tlo_a = (uint32_t)__cvta_generic_to_shared(W1T_LO);
    const uint32_t WS1hi_a = (uint32_t)__cvta_generic_to_shared(WS1_HI);
    const uint32_t WS1lo_a = (uint32_t)__cvta_generic_to_shared(WS1_LO);
    const uint32_t WREhi_a = (uint32_t)__cvta_generic_to_shared(WRE_HI);
    const uint32_t WRElo_a = (uint32_t)__cvta_generic_to_shared(WRE_LO);
    const uint32_t WAThi_a = (uint32_t)__cvta_generic_to_shared(WAT_HI);
    const uint32_t WATlo_a = (uint32_t)__cvta_generic_to_shared(WAT_LO);

    for (int jt = 0; jt < 4; jt++) {
        const int j0 = jt * 64;
        // ---- stage r tile as split bf16 (cols 9..15 stay zero) ----
        for (int idx = tid; idx < 576; idx += 256) {
            const int j = idx / 9, d = idx - j * 9;
            __nv_bfloat16 hi, lo;
            split1(rrow[j0 * 9 + idx], hi, lo);
            RT_HI[j * 24 + d] = hi;
            RT_LO[j * 24 + d] = lo;
        }
        __syncthreads();

        // ---- Phase A (MMA, all 8 warps): H = relu(r @ W1F + B1F) ----
        {
            const int nh = wid >> 2;     // n-half: 16 of 32 channels
            uint32_t rahi[4], ralo[4], wh[4], wl[4];
            ldsm_x4(rahi[0], rahi[1], rahi[2], rahi[3], RThi_a + (uint32_t)aoff24 * 2u);
            ldsm_x4(ralo[0], ralo[1], ralo[2], ralo[3], RTlo_a + (uint32_t)aoff24 * 2u);
            const uint32_t woff = (uint32_t)((nh * 16 + brow) * 24 + bcol) * 2u;
            ldsm_x4(wh[0], wh[1], wh[2], wh[3], W1Thi_a + woff);
            ldsm_x4(wl[0], wl[1], wl[2], wl[3], W1Tlo_a + woff);
            float acc[2][4];
#pragma unroll
            for (int t = 0; t < 2; t++)
#pragma unroll
                for (int u = 0; u < 4; u++) acc[t][u] = 0.f;
            mma_bf16(acc[0], rahi, wh[0], wh[1]);
            mma_bf16(acc[1], rahi, wh[2], wh[3]);
            mma_bf16(acc[0], rahi, wl[0], wl[1]);
            mma_bf16(acc[1], rahi, wl[2], wl[3]);
            mma_bf16(acc[0], ralo, wh[0], wh[1]);
            mma_bf16(acc[1], ralo, wh[2], wh[3]);
            const int r0 = m0 + gid;
#pragma unroll
            for (int t = 0; t < 2; t++) {
                const int c = (nh * 2 + t) * 8 + 2 * tig;
                const float2 bf2 = *(const float2*)(B1F + c);
                uint32_t hi, lo;
                split2(fmaxf(acc[t][0] + bf2.x, 0.f), fmaxf(acc[t][1] + bf2.y, 0.f), hi, lo);
                *(uint32_t*)(H_HI + r0 * 40 + c) = hi;
                *(uint32_t*)(H_LO + r0 * 40 + c) = lo;
                split2(fmaxf(acc[t][2] + bf2.x, 0.f), fmaxf(acc[t][3] + bf2.y, 0.f), hi, lo);
                *(uint32_t*)(H_HI + (r0 + 8) * 40 + c) = hi;
                *(uint32_t*)(H_LO + (r0 + 8) * 40 + c) = lo;
            }
        }
        __syncthreads();

        // ---- A fragments of H ----
        uint32_t ahi[2][4], alo[2][4];
#pragma unroll
        for (int ks = 0; ks < 2; ks++) {
            ldsm_x4(ahi[ks][0], ahi[ks][1], ahi[ks][2], ahi[ks][3],
                    Hhi_a + (uint32_t)(aoff40 + ks * 16) * 2u);
            ldsm_x4(alo[ks][0], alo[ks][1], alo[ks][2], alo[ks][3],
                    Hlo_a + (uint32_t)(aoff40 + ks * 16) * 2u);
        }

        if (wid < 4) {
            // ======== warps 0-3: S1 (chained) then Sim ========
            float accS[8][4];
#pragma unroll
            for (int t = 0; t < 8; t++)
#pragma unroll
                for (int u = 0; u < 4; u++) accS[t][u] = 0.f;
#pragma unroll
            for (int g = 0; g < 2; g++)
#pragma unroll
                for (int ks = 0; ks < 2; ks++)
                    MMA_GROUP4(accS, g * 4, ahi[ks], alo[ks], WS1hi_a, WS1lo_a, 40, ks * 16);
            // epilogue: S1 = relu(accS + qa - ka + b1a) -> A-frags
            const int r0 = m0 + gid;
            const float* ka0p = &g_proj[(b * TT + j0 + r0) * 128 + 64];
            const float* ka1p = &g_proj[(b * TT + j0 + r0 + 8) * 128 + 64];
            uint32_t s1hi[4][4], s1lo[4][4];
#pragma unroll
            for (int kg = 0; kg < 4; kg++) {
#pragma unroll
                for (int half = 0; half < 2; half++) {
                    const int tt = 2 * kg + half;
                    const int c = tt * 8 + 2 * tig;
                    const float2 qa2 = *(const float2*)(QA + c);
                    const float2 ba2 = *(const float2*)(B1A + c);
                    const float2 ka0 = *(const float2*)(ka0p + c);
                    const float2 ka1 = *(const float2*)(ka1p + c);
                    const float s00 = fmaxf(accS[tt][0] + qa2.x - ka0.x + ba2.x, 0.f);
                    const float s01 = fmaxf(accS[tt][1] + qa2.y - ka0.y + ba2.y, 0.f);
                    const float s10 = fmaxf(accS[tt][2] + qa2.x - ka1.x + ba2.x, 0.f);
                    const float s11 = fmaxf(accS[tt][3] + qa2.y - ka1.y + ba2.y, 0.f);
                    split2(s00, s01, s1hi[kg][half * 2], s1lo[kg][half * 2]);
                    split2(s10, s11, s1hi[kg][half * 2 + 1], s1lo[kg][half * 2 + 1]);
                }
            }
            // Sim = S1 @ W2A
            float accD[8][4];
#pragma unroll
            for (int t = 0; t < 8; t++)
#pragma unroll
                for (int u = 0; u < 4; u++) accD[t][u] = 0.f;
#pragma unroll
            for (int g = 0; g < 2; g++)
#pragma unroll
                for (int ks = 0; ks < 4; ks++)
                    MMA_GROUP4(accD, g * 4, s1hi[ks], s1lo[ks], WAThi_a, WATlo_a, 80, ks * 16);
#pragma unroll
            for (int tt = 0; tt < 8; tt++) {
                const int c = tt * 8 + 2 * tig;
                *(float2*)(SIMb + r0 * 68 + c) = make_float2(accD[tt][0], accD[tt][1]);
                *(float2*)(SIMb + (r0 + 8) * 68 + c) = make_float2(accD[tt][2], accD[tt][3]);
            }
        } else {
            // ======== warps 4-7: RE, fuse vg -> vj ========
            float accR[8][4];
#pragma unroll
            for (int t = 0; t < 8; t++)
#pragma unroll
                for (int u = 0; u < 4; u++) accR[t][u] = 0.f;
#pragma unroll
            for (int g = 0; g < 2; g++)
#pragma unroll
                for (int ks = 0; ks < 2; ks++)
                    MMA_GROUP4(accR, g * 4, ahi[ks], alo[ks], WREhi_a, WRElo_a, 40, ks * 16);
            const int r0 = m0 + gid;
            const float* v0p = &g_qkv[(b * TT + j0 + r0) * 192 + 128];
            const float* v1p = &g_qkv[(b * TT + j0 + r0 + 8) * 192 + 128];
#pragma unroll
            for (int tt = 0; tt < 8; tt++) {
                const int c = tt * 8 + 2 * tig;
                const float2 bf2 = *(const float2*)(B2F + c);
                const float2 vg0 = *(const float2*)(v0p + c);
                const float2 vg1 = *(const float2*)(v1p + c);
                *(float2*)(REb + r0 * 68 + c) =
                    make_float2(accR[tt][0] + bf2.x + vg0.x, accR[tt][1] + bf2.y + vg0.y);
                *(float2*)(REb + (r0 + 8) * 68 + c) =
                    make_float2(accR[tt][2] + bf2.x + vg1.x, accR[tt][3] + bf2.y + vg1.y);
            }
        }
        __syncthreads();

        // ---- online softmax accumulate (SIMT, all threads) ----
        {
            const float4 bb = *(const float4*)(B2A + c0);
#pragma unroll
            for (int i = 0; i < 4; i++) {
                const int lj = jr * 4 + i;
                const float4 sv = *(const float4*)(SIMb + lj * 68 + c0);
                const float4 vj4 = *(const float4*)(REb + lj * 68 + c0);
                float s[4]  = { sv.x + bb.x, sv.y + bb.y, sv.z + bb.z, sv.w + bb.w };
#pragma unroll
                for (int u = 0; u < 4; u++) {
                    const float nm = fmaxf(m4[u], s[u]);
                    const float f = __expf(m4[u] - nm);
                    const float e = __expf(s[u] - nm);
                    l4[u] = l4[u] * f + e;
                    a4[u] = a4[u] * f + e * ((const float*)&vj4)[u];
                    m4[u] = nm;
                }
            }
        }
        __syncthreads();   // protect RT/H/SIM/RE overwrite next iter
    }

    // ---- cross-jr softmax combine (partials in RE region) ----
#pragma unroll
    for (int u = 0; u < 4; u++) {
        REb[jr * 64 + c0 + u]        = m4[u];
        REb[1024 + jr * 64 + c0 + u] = l4[u];
        REb[2048 + jr * 64 + c0 + u] = a4[u];
    }
    __syncthreads();
    if (tid < 64) {
        float M = -1e30f;
#pragma unroll
        for (int p = 0; p < 16; p++) M = fmaxf(M, REb[p * 64 + tid]);
        float L = 0.f, A = 0.f;
#pragma unroll
        for (int p = 0; p < 16; p++) {
            const float f = __expf(REb[p * 64 + tid] - M);
            L += REb[1024 + p * 64 + tid] * f;
            A += REb[2048 + p * 64 + tid] * f;
        }
        out[row * 64 + tid] = A / L;
    }
}

// ---------------------------------------------------------------------------
extern "C" void kernel_launch(void* const* d_in, const int* in_sizes, int n_in,
                              void* d_out, int out_size) {
    (void)in_sizes; (void)n_in; (void)out_size;
    const float* x      = (const float*)d_in[0];
    const float* r      = (const float*)d_in[1];
    const float* w_qkv  = (const float*)d_in[2];
    const float* tpr_w1 = (const float*)d_in[3];
    const float* tpr_b1 = (const float*)d_in[4];
    const float* bn_g   = (const float*)d_in[5];
    const float* bn_b   = (const float*)d_in[6];
    const float* bn_m   = (const float*)d_in[7];
    const float* bn_v   = (const float*)d_in[8];
    const float* tpr_w2 = (const float*)d_in[9];
    const float* tpr_b2 = (const float*)d_in[10];
    const float* aw1    = (const float*)d_in[11];
    const float* ab1    = (const float*)d_in[12];
    const float* aw2    = (const float*)d_in[13];
    const float* ab2    = (const float*)d_in[14];
    float* out = (float*)d_out;

    cudaFuncSetAttribute(va_kernel, cudaFuncAttributeMaxDynamicSharedMemorySize,
                         SMEM_BYTES);

    qkv_kernel<<<NROW, 192>>>(x, w_qkv);
    proj_kernel<<<NROW, 128>>>(aw1);
    w2p_kernel<<<1, 64>>>(tpr_w2, tpr_b2, aw1, ab1);
    va_kernel<<<NROW, 256, SMEM_BYTES>>>(r, tpr_w1, tpr_b1, bn_g, bn_b, bn_m, bn_v,
                                         tpr_w2, tpr_b2, aw2, ab2, out);
}

// round 7
// speedup vs baseline: 1.5334x; 1.0265x over previous
#include <cuda_runtime.h>
#include <cuda_bf16.h>
#include <math.h>
#include <stdint.h>

#define TT 256
#define NROW 2048            // B*T
#define BN_EPS 1e-5f

// scratch
__device__ float g_qkv[NROW * 192];    // q|k|v per row
__device__ float g_proj[NROW * 128];   // qA|kA per row  ({q,k}@attn_w1)
__device__ float g_w2p[32 * 64];       // tpr_w2 @ attn_w1
__device__ float g_b1a[64];            // tpr_b2 @ attn_w1 + attn_b1

// ---------------------------------------------------------------------------
__global__ __launch_bounds__(192) void qkv_kernel(const float* __restrict__ x,
                                                  const float* __restrict__ w) {
    __shared__ float xs[128];
    const int row = blockIdx.x;
    const int tid = threadIdx.x;
    if (tid < 128) xs[tid] = x[row * 128 + tid];
    __syncthreads();
    float a0 = 0.f, a1 = 0.f, a2 = 0.f, a3 = 0.f;
#pragma unroll 8
    for (int d = 0; d < 128; d += 4) {
        a0 += xs[d + 0] * w[(d + 0) * 192 + tid];
        a1 += xs[d + 1] * w[(d + 1) * 192 + tid];
        a2 += xs[d + 2] * w[(d + 2) * 192 + tid];
        a3 += xs[d + 3] * w[(d + 3) * 192 + tid];
    }
    g_qkv[row * 192 + tid] = (a0 + a1) + (a2 + a3);
}

__global__ __launch_bounds__(128) void proj_kernel(const float* __restrict__ aw1) {
    __shared__ float qk[128];
    const int row = blockIdx.x;
    const int tid = threadIdx.x;
    qk[tid] = g_qkv[row * 192 + tid];
    __syncthreads();
    const float* src = (tid < 64) ? qk : (qk + 64);
    const int col = tid & 63;
    float a0 = 0.f, a1 = 0.f;
#pragma unroll 8
    for (int d = 0; d < 64; d += 2) {
        a0 += src[d + 0] * aw1[(d + 0) * 64 + col];
        a1 += src[d + 1] * aw1[(d + 1) * 64 + col];
    }
    g_proj[row * 128 + tid] = a0 + a1;
}

__global__ __launch_bounds__(64) void w2p_kernel(const float* __restrict__ tpr_w2,
                                                 const float* __restrict__ tpr_b2,
                                                 const float* __restrict__ aw1,
                                                 const float* __restrict__ ab1) {
    __shared__ float w2s[2048];
    __shared__ float a1s[4096];
    const int tid = threadIdx.x;
    for (int i = tid; i < 2048; i += 64) w2s[i] = tpr_w2[i];
    for (int i = tid; i < 4096; i += 64) a1s[i] = aw1[i];
    __syncthreads();
    const int c = tid;
    for (int h = 0; h < 32; h++) {
        float acc = 0.f;
#pragma unroll 8
        for (int d = 0; d < 64; d++) acc += w2s[h * 64 + d] * a1s[d * 64 + c];
        g_w2p[h * 64 + c] = acc;
    }
    float accb = ab1[c];
#pragma unroll 8
    for (int d = 0; d < 64; d++) accb += tpr_b2[d] * a1s[d * 64 + c];
    g_b1a[c] = accb;
}

// ---------------------------------------------------------------------------
// helpers
// ---------------------------------------------------------------------------
__device__ __forceinline__ void mma_bf16(float* d, const uint32_t* a,
                                         uint32_t b0, uint32_t b1) {
    asm volatile(
        "mma.sync.aligned.m16n8k16.row.col.f32.bf16.bf16.f32 "
        "{%0,%1,%2,%3}, {%4,%5,%6,%7}, {%8,%9}, {%0,%1,%2,%3};"
        : "+f"(d[0]), "+f"(d[1]), "+f"(d[2]), "+f"(d[3])
        : "r"(a[0]), "r"(a[1]), "r"(a[2]), "r"(a[3]), "r"(b0), "r"(b1));
}

__device__ __forceinline__ void ldsm_x4(uint32_t& r0, uint32_t& r1,
                                        uint32_t& r2, uint32_t& r3, uint32_t addr) {
    asm volatile("ldmatrix.sync.aligned.m8n8.x4.shared.b16 {%0,%1,%2,%3}, [%4];"
                 : "=r"(r0), "=r"(r1), "=r"(r2), "=r"(r3) : "r"(addr));
}

__device__ __forceinline__ uint32_t b2u(__nv_bfloat162 v) {
    return *reinterpret_cast<uint32_t*>(&v);
}

__device__ __forceinline__ void split2(float x, float y, uint32_t& hi, uint32_t& lo) {
    __nv_bfloat16 hx = __float2bfloat16_rn(x);
    __nv_bfloat16 hy = __float2bfloat16_rn(y);
    float rx = x - __bfloat162float(hx);
    float ry = y - __bfloat162float(hy);
    __nv_bfloat162 h2; h2.x = hx; h2.y = hy;
    hi = b2u(h2);
    lo = b2u(__floats2bfloat162_rn(rx, ry));
}

__device__ __forceinline__ void split1(float x, __nv_bfloat16& hi, __nv_bfloat16& lo) {
    hi = __float2bfloat16_rn(x);
    lo = __float2bfloat16_rn(x - __bfloat162float(hi));
}

// 4 n-tiles, 3-term bf16x3 split, dependency distance 4 (12 MMAs)
#define MMA_GROUP4(ACC, T0, AH, AL, WHI, WLO, STRIDE, KOFF)                       \
    do {                                                                          \
        uint32_t bh[8], bl[8];                                                    \
        ldsm_x4(bh[0], bh[1], bh[2], bh[3],                                       \
                WHI + (uint32_t)((((T0) * 8 + brow) * (STRIDE)) + (KOFF) + bcol) * 2u); \
        ldsm_x4(bh[4], bh[5], bh[6], bh[7],                                       \
                WHI + (uint32_t)(((((T0) + 2) * 8 + brow) * (STRIDE)) + (KOFF) + bcol) * 2u); \
        ldsm_x4(bl[0], bl[1], bl[2], bl[3],                                       \
                WLO + (uint32_t)((((T0) * 8 + brow) * (STRIDE)) + (KOFF) + bcol) * 2u); \
        ldsm_x4(bl[4], bl[5], bl[6], bl[7],                                       \
                WLO + (uint32_t)(((((T0) + 2) * 8 + brow) * (STRIDE)) + (KOFF) + bcol) * 2u); \
        mma_bf16(ACC[(T0) + 0], AH, bh[0], bh[1]);                                \
        mma_bf16(ACC[(T0) + 1], AH, bh[2], bh[3]);                                \
        mma_bf16(ACC[(T0) + 2], AH, bh[4], bh[5]);                                \
        mma_bf16(ACC[(T0) + 3], AH, bh[6], bh[7]);                                \
        mma_bf16(ACC[(T0) + 0], AH, bl[0], bl[1]);                                \
        mma_bf16(ACC[(T0) + 1], AH, bl[2], bl[3]);                                \
        mma_bf16(ACC[(T0) + 2], AH, bl[4], bl[5]);                                \
        mma_bf16(ACC[(T0) + 3], AH, bl[6], bl[7]);                                \
        mma_bf16(ACC[(T0) + 0], AL, bh[0], bh[1]);                                \
        mma_bf16(ACC[(T0) + 1], AL, bh[2], bh[3]);                                \
        mma_bf16(ACC[(T0) + 2], AL, bh[4], bh[5]);                                \
        mma_bf16(ACC[(T0) + 3], AL, bh[6], bh[7]);                                \
    } while (0)

// ---------------------------------------------------------------------------
// Shared memory byte offsets (16B aligned)
// ---------------------------------------------------------------------------
#define SO_WRE_HI 0          // [64][40] bf16  W2T^T
#define SO_WRE_LO 5120
#define SO_WS1_HI 10240      // [64][40] bf16  W2P^T
#define SO_WS1_LO 15360
#define SO_WAT_HI 20480      // [64][72] bf16  W2A^T
#define SO_WAT_LO 29696
#define SO_S1X_HI 38912      // [64][72] bf16  S1 exchange
#define SO_S1X_LO 48128
#define SO_RT_HI  57344      // [64][24] bf16  r tile (k padded 16)
#define SO_RT_LO  60416
#define SO_W1T_HI 63488      // [32][24] bf16  BN-folded W1^T
#define SO_W1T_LO 65024
#define SO_RE     66560      // [64][68] fp32  vj (+ final combine)
#define SO_SIM    83968      // [64][68] fp32  Sim
#define SO_B1F    101376     // 32 fp32
#define SO_B2F    101504     // 64
#define SO_B1A    101760     // 64
#define SO_B2A    102016     // 64
#define SO_QA     102272     // 64
#define SMEM_BYTES 102528

__global__ __launch_bounds__(256, 2) void va_kernel(
    const float* __restrict__ r,
    const float* __restrict__ tpr_w1, const float* __restrict__ tpr_b1,
    const float* __restrict__ bn_g, const float* __restrict__ bn_b,
    const float* __restrict__ bn_m, const float* __restrict__ bn_v,
    const float* __restrict__ tpr_w2, const float* __restrict__ tpr_b2,
    const float* __restrict__ aw2, const float* __restrict__ ab2,
    float* __restrict__ out)
{
    extern __shared__ __align__(16) char sb[];
    __nv_bfloat16* WRE_HI = (__nv_bfloat16*)(sb + SO_WRE_HI);
    __nv_bfloat16* WRE_LO = (__nv_bfloat16*)(sb + SO_WRE_LO);
    __nv_bfloat16* WS1_HI = (__nv_bfloat16*)(sb + SO_WS1_HI);
    __nv_bfloat16* WS1_LO = (__nv_bfloat16*)(sb + SO_WS1_LO);
    __nv_bfloat16* WAT_HI = (__nv_bfloat16*)(sb + SO_WAT_HI);
    __nv_bfloat16* WAT_LO = (__nv_bfloat16*)(sb + SO_WAT_LO);
    __nv_bfloat16* S1X_HI = (__nv_bfloat16*)(sb + SO_S1X_HI);
    __nv_bfloat16* S1X_LO = (__nv_bfloat16*)(sb + SO_S1X_LO);
    __nv_bfloat16* RT_HI  = (__nv_bfloat16*)(sb + SO_RT_HI);
    __nv_bfloat16* RT_LO  = (__nv_bfloat16*)(sb + SO_RT_LO);
    __nv_bfloat16* W1T_HI = (__nv_bfloat16*)(sb + SO_W1T_HI);
    __nv_bfloat16* W1T_LO = (__nv_bfloat16*)(sb + SO_W1T_LO);
    float* REb  = (float*)(sb + SO_RE);
    float* SIMb = (float*)(sb + SO_SIM);
    float* B1F  = (float*)(sb + SO_B1F);
    float* B2F  = (float*)(sb + SO_B2F);
    float* B1A  = (float*)(sb + SO_B1A);
    float* B2A  = (float*)(sb + SO_B2A);
    float* QA   = (float*)(sb + SO_QA);

    const int tid = threadIdx.x;
    const int row = blockIdx.x;          // b*T + i
    const int b = row >> 8;
    const int wid = tid >> 5, lane = tid & 31;
    const int gid = lane >> 2, tig = lane & 3;
    const int arow = lane & 7, asel = lane >> 3;

    // ---- stage weights (once) ----
    for (int idx = tid; idx < 64 * 24; idx += 256) { RT_HI[idx] = __nv_bfloat16(0.f); RT_LO[idx] = __nv_bfloat16(0.f); }
    for (int idx = tid; idx < 32 * 24; idx += 256) { W1T_HI[idx] = __nv_bfloat16(0.f); W1T_LO[idx] = __nv_bfloat16(0.f); }
    if (tid < 32) {
        float sc = bn_g[tid] * rsqrtf(bn_v[tid] + BN_EPS);
        B1F[tid] = (tpr_b1[tid] - bn_m[tid]) * sc + bn_b[tid];
    }
    if (tid < 64) {
        B2F[tid] = tpr_b2[tid];
        B1A[tid] = g_b1a[tid];
        B2A[tid] = ab2[tid];
        QA[tid]  = g_proj[row * 128 + tid];
    }
    __syncthreads();
    for (int idx = tid; idx < 288; idx += 256) {      // W1FT (BN-folded, transposed)
        const int d = idx >> 5, n = idx & 31;
        const float sc = bn_g[n] * rsqrtf(bn_v[n] + BN_EPS);
        __nv_bfloat16 hi, lo;
        split1(tpr_w1[idx] * sc, hi, lo);
        W1T_HI[n * 24 + d] = hi;
        W1T_LO[n * 24 + d] = lo;
    }
    for (int idx = tid; idx < 2048; idx += 256) {     // W2T^T, W2P^T (stride 40)
        const int n = idx >> 5, k = idx & 31;
        __nv_bfloat16 hi, lo;
        split1(tpr_w2[k * 64 + n], hi, lo);
        WRE_HI[n * 40 + k] = hi; WRE_LO[n * 40 + k] = lo;
        split1(g_w2p[k * 64 + n], hi, lo);
        WS1_HI[n * 40 + k] = hi; WS1_LO[n * 40 + k] = lo;
    }
    for (int idx = tid; idx < 4096; idx += 256) {     // W2A^T (stride 72)
        const int n = idx >> 6, k = idx & 63;
        __nv_bfloat16 hi, lo;
        split1(aw2[k * 64 + n], hi, lo);
        WAT_HI[n * 72 + k] = hi; WAT_LO[n * 72 + k] = lo;
    }

    const int jr = tid >> 4;             // 0..15
    const int c0 = (tid & 15) << 2;      // 0..60

    float m4[4], l4[4], a4[4];
#pragma unroll
    for (int u = 0; u < 4; u++) { m4[u] = -1e30f; l4[u] = 0.f; a4[u] = 0.f; }

    const float* rrow = r + (size_t)row * (TT * 9);

    const int wmod = wid & 3;            // m-tile (warps w and w+4 share it)
    const int nq = wid >> 2;             // n-half owner for Sim phase
    const int m0 = wmod * 16;
    const int r0 = m0 + gid;
    const int brow = arow + (asel >> 1) * 8;
    const int bcol = (asel & 1) * 8;
    const int aoff24 = (m0 + arow + (asel & 1) * 8) * 24 + (asel >> 1) * 8;
    const int aoff72 = (m0 + arow + (asel & 1) * 8) * 72 + (asel >> 1) * 8;

    const uint32_t RThi_a  = (uint32_t)__cvta_generic_to_shared(RT_HI);
    const uint32_t RTlo_a  = (uint32_t)__cvta_generic_to_shared(RT_LO);
    const uint32_t W1Thi_a = (uint32_t)__cvta_generic_to_shared(W1T_HI);
    const uint32_t W1Tlo_a = (uint32_t)__cvta_generic_to_shared(W1T_LO);
    const uint32_t WS1hi_a = (uint32_t)__cvta_generic_to_shared(WS1_HI);
    const uint32_t WS1lo_a = (uint32_t)__cvta_generic_to_shared(WS1_LO);
    const uint32_t WREhi_a = (uint32_t)__cvta_generic_to_shared(WRE_HI);
    const uint32_t WRElo_a = (uint32_t)__cvta_generic_to_shared(WRE_LO);
    const uint32_t WAThi_a = (uint32_t)__cvta_generic_to_shared(WAT_HI) + (uint32_t)(nq * 32 * 72 * 2);
    const uint32_t WATlo_a = (uint32_t)__cvta_generic_to_shared(WAT_LO) + (uint32_t)(nq * 32 * 72 * 2);
    const uint32_t S1Xhi_a = (uint32_t)__cvta_generic_to_shared(S1X_HI);
    const uint32_t S1Xlo_a = (uint32_t)__cvta_generic_to_shared(S1X_LO);

    for (int jt = 0; jt < 4; jt++) {
        const int j0 = jt * 64;
        // ---- stage r tile as split bf16 ----
        for (int idx = tid; idx < 576; idx += 256) {
            const int j = idx / 9, d = idx - j * 9;
            __nv_bfloat16 hi, lo;
            split1(rrow[j0 * 9 + idx], hi, lo);
            RT_HI[j * 24 + d] = hi;
            RT_LO[j * 24 + d] = lo;
        }
        __syncthreads();                                       // sync1

        // ---- Phase A (regs, every warp): H = relu(r @ W1F + B1F) for its 16 rows ----
        uint32_t Hhi[2][4], Hlo[2][4];
        {
            uint32_t rahi[4], ralo[4];
            ldsm_x4(rahi[0], rahi[1], rahi[2], rahi[3], RThi_a + (uint32_t)aoff24 * 2u);
            ldsm_x4(ralo[0], ralo[1], ralo[2], ralo[3], RTlo_a + (uint32_t)aoff24 * 2u);
            float accA[4][4];
#pragma unroll
            for (int t = 0; t < 4; t++)
#pragma unroll
                for (int u = 0; u < 4; u++) accA[t][u] = 0.f;
            MMA_GROUP4(accA, 0, rahi, ralo, W1Thi_a, W1Tlo_a, 24, 0);
            // repack accumulators (rows r0/r0+8, cols t*8+2tig..+1) into A-frags
#pragma unroll
            for (int ks = 0; ks < 2; ks++) {
                const int t0 = 2 * ks, t1 = 2 * ks + 1;
                const float2 bb0 = *(const float2*)(B1F + t0 * 8 + 2 * tig);
                const float2 bb1 = *(const float2*)(B1F + t1 * 8 + 2 * tig);
                split2(fmaxf(accA[t0][0] + bb0.x, 0.f), fmaxf(accA[t0][1] + bb0.y, 0.f),
                       Hhi[ks][0], Hlo[ks][0]);
                split2(fmaxf(accA[t0][2] + bb0.x, 0.f), fmaxf(accA[t0][3] + bb0.y, 0.f),
                       Hhi[ks][1], Hlo[ks][1]);
                split2(fmaxf(accA[t1][0] + bb1.x, 0.f), fmaxf(accA[t1][1] + bb1.y, 0.f),
                       Hhi[ks][2], Hlo[ks][2]);
                split2(fmaxf(accA[t1][2] + bb1.x, 0.f), fmaxf(accA[t1][3] + bb1.y, 0.f),
                       Hhi[ks][3], Hlo[ks][3]);
            }
        }

        uint32_t s1hi[4][4], s1lo[4][4];   // S1 A-frags (k=64)
        if (wid < 4) {
            // ---- warps 0-3: S1 = relu(H@W2P + qa - ka + b1a) ----
            float accS[8][4];
#pragma unroll
            for (int t = 0; t < 8; t++)
#pragma unroll
                for (int u = 0; u < 4; u++) accS[t][u] = 0.f;
#pragma unroll
            for (int g = 0; g < 2; g++)
#pragma unroll
                for (int ks = 0; ks < 2; ks++)
                    MMA_GROUP4(accS, g * 4, Hhi[ks], Hlo[ks], WS1hi_a, WS1lo_a, 40, ks * 16);
            const float* ka0p = &g_proj[(b * TT + j0 + r0) * 128 + 64];
            const float* ka1p = &g_proj[(b * TT + j0 + r0 + 8) * 128 + 64];
#pragma unroll
            for (int kg = 0; kg < 4; kg++) {
#pragma unroll
                for (int half = 0; half < 2; half++) {
                    const int tt = 2 * kg + half;
                    const int c = tt * 8 + 2 * tig;
                    const float2 qa2 = *(const float2*)(QA + c);
                    const float2 ba2 = *(const float2*)(B1A + c);
                    const float2 ka0 = *(const float2*)(ka0p + c);
                    const float2 ka1 = *(const float2*)(ka1p + c);
                    const float s00 = fmaxf(accS[tt][0] + qa2.x - ka0.x + ba2.x, 0.f);
                    const float s01 = fmaxf(accS[tt][1] + qa2.y - ka0.y + ba2.y, 0.f);
                    const float s10 = fmaxf(accS[tt][2] + qa2.x - ka1.x + ba2.x, 0.f);
                    const float s11 = fmaxf(accS[tt][3] + qa2.y - ka1.y + ba2.y, 0.f);
                    uint32_t hi0, lo0, hi1, lo1;
                    split2(s00, s01, hi0, lo0);
                    split2(s10, s11, hi1, lo1);
                    s1hi[kg][half * 2] = hi0;     s1lo[kg][half * 2] = lo0;
                    s1hi[kg][half * 2 + 1] = hi1; s1lo[kg][half * 2 + 1] = lo1;
                    *(uint32_t*)(S1X_HI + r0 * 72 + c) = hi0;
                    *(uint32_t*)(S1X_LO + r0 * 72 + c) = lo0;
                    *(uint32_t*)(S1X_HI + (r0 + 8) * 72 + c) = hi1;
                    *(uint32_t*)(S1X_LO + (r0 + 8) * 72 + c) = lo1;
                }
            }
        } else {
            // ---- warps 4-7: RE = H@W2T + b2f ; vj = RE + vg -> smem ----
            float accR[8][4];
#pragma unroll
            for (int t = 0; t < 8; t++)
#pragma unroll
                for (int u = 0; u < 4; u++) accR[t][u] = 0.f;
#pragma unroll
            for (int g = 0; g < 2; g++)
#pragma unroll
                for (int ks = 0; ks < 2; ks++)
                    MMA_GROUP4(accR, g * 4, Hhi[ks], Hlo[ks], WREhi_a, WRElo_a, 40, ks * 16);
            const float* v0p = &g_qkv[(b * TT + j0 + r0) * 192 + 128];
            const float* v1p = &g_qkv[(b * TT + j0 + r0 + 8) * 192 + 128];
#pragma unroll
            for (int tt = 0; tt < 8; tt++) {
                const int c = tt * 8 + 2 * tig;
                const float2 bf2 = *(const float2*)(B2F + c);
                const float2 vg0 = *(const float2*)(v0p + c);
                const float2 vg1 = *(const float2*)(v1p + c);
                *(float2*)(REb + r0 * 68 + c) =
                    make_float2(accR[tt][0] + bf2.x + vg0.x, accR[tt][1] + bf2.y + vg0.y);
                *(float2*)(REb + (r0 + 8) * 68 + c) =
                    make_float2(accR[tt][2] + bf2.x + vg1.x, accR[tt][3] + bf2.y + vg1.y);
            }
        }
        __syncthreads();                                       // sync2

        // ---- Sim = S1 @ W2A, all 8 warps, n-half nq each ----
        {
            if (wid >= 4) {
#pragma unroll
                for (int ks = 0; ks < 4; ks++) {
                    ldsm_x4(s1hi[ks][0], s1hi[ks][1], s1hi[ks][2], s1hi[ks][3],
                            S1Xhi_a + (uint32_t)(aoff72 + ks * 16) * 2u);
                    ldsm_x4(s1lo[ks][0], s1lo[ks][1], s1lo[ks][2], s1lo[ks][3],
                            S1Xlo_a + (uint32_t)(aoff72 + ks * 16) * 2u);
                }
            }
            float accD[4][4];
#pragma unroll
            for (int t = 0; t < 4; t++)
#pragma unroll
                for (int u = 0; u < 4; u++) accD[t][u] = 0.f;
#pragma unroll
            for (int ks = 0; ks < 4; ks++)
                MMA_GROUP4(accD, 0, s1hi[ks], s1lo[ks], WAThi_a, WATlo_a, 72, ks * 16);
#pragma unroll
            for (int tt = 0; tt < 4; tt++) {
                const int c = nq * 32 + tt * 8 + 2 * tig;
                *(float2*)(SIMb + r0 * 68 + c) = make_float2(accD[tt][0], accD[tt][1]);
                *(float2*)(SIMb + (r0 + 8) * 68 + c) = make_float2(accD[tt][2], accD[tt][3]);
            }
        }
        __syncthreads();                                       // sync3

        // ---- online softmax accumulate (SIMT, all threads) ----
        {
            const float4 bb = *(const float4*)(B2A + c0);
#pragma unroll
            for (int i = 0; i < 4; i++) {
                const int lj = jr * 4 + i;
                const float4 sv = *(const float4*)(SIMb + lj * 68 + c0);
                const float4 vj4 = *(const float4*)(REb + lj * 68 + c0);
                float s[4] = { sv.x + bb.x, sv.y + bb.y, sv.z + bb.z, sv.w + bb.w };
#pragma unroll
                for (int u = 0; u < 4; u++) {
                    const float nm = fmaxf(m4[u], s[u]);
                    const float f = __expf(m4[u] - nm);
                    const float e = __expf(s[u] - nm);
                    l4[u] = l4[u] * f + e;
                    a4[u] = a4[u] * f + e * ((const float*)&vj4)[u];
                    m4[u] = nm;
                }
            }
        }
        __syncthreads();                                       // guard buffer reuse
    }

    // ---- cross-jr softmax combine (partials in RE region) ----
#pragma unroll
    for (int u = 0; u < 4; u++) {
        REb[jr * 64 + c0 + u]        = m4[u];
        REb[1024 + jr * 64 + c0 + u] = l4[u];
        REb[2048 + jr * 64 + c0 + u] = a4[u];
    }
    __syncthreads();
    if (tid < 64) {
        float M = -1e30f;
#pragma unroll
        for (int p = 0; p < 16; p++) M = fmaxf(M, REb[p * 64 + tid]);
        float L = 0.f, A = 0.f;
#pragma unroll
        for (int p = 0; p < 16; p++) {
            const float f = __expf(REb[p * 64 + tid] - M);
            L += REb[1024 + p * 64 + tid] * f;
            A += REb[2048 + p * 64 + tid] * f;
        }
        out[row * 64 + tid] = A / L;
    }
}

// ---------------------------------------------------------------------------
extern "C" void kernel_launch(void* const* d_in, const int* in_sizes, int n_in,
                              void* d_out, int out_size) {
    (void)in_sizes; (void)n_in; (void)out_size;
    const float* x      = (const float*)d_in[0];
    const float* r      = (const float*)d_in[1];
    const float* w_qkv  = (const float*)d_in[2];
    const float* tpr_w1 = (const float*)d_in[3];
    const float* tpr_b1 = (const float*)d_in[4];
    const float* bn_g   = (const float*)d_in[5];
    const float* bn_b   = (const float*)d_in[6];
    const float* bn_m   = (const float*)d_in[7];
    const float* bn_v   = (const float*)d_in[8];
    const float* tpr_w2 = (const float*)d_in[9];
    const float* tpr_b2 = (const float*)d_in[10];
    const float* aw1    = (const float*)d_in[11];
    const float* ab1    = (const float*)d_in[12];
    const float* aw2    = (const float*)d_in[13];
    const float* ab2    = (const float*)d_in[14];
    float* out = (float*)d_out;

    cudaFuncSetAttribute(va_kernel, cudaFuncAttributeMaxDynamicSharedMemorySize,
                         SMEM_BYTES);

    qkv_kernel<<<NROW, 192>>>(x, w_qkv);
    proj_kernel<<<NROW, 128>>>(aw1);
    w2p_kernel<<<1, 64>>>(tpr_w2, tpr_b2, aw1, ab1);
    va_kernel<<<NROW, 256, SMEM_BYTES>>>(r, tpr_w1, tpr_b1, bn_g, bn_b, bn_m, bn_v,
                                         tpr_w2, tpr_b2, aw2, ab2, out);
}

// round 9
// speedup vs baseline: 2.1386x; 1.3947x over previous
#include <cuda_runtime.h>
#include <cuda_bf16.h>
#include <math.h>
#include <stdint.h>

#define TT 256
#define NROW 2048            // B*T
#define BN_EPS 1e-5f
#define GRID_PERS 296        // 148 SMs x 2 CTAs = one full wave

// scratch
__device__ float g_qkv[NROW * 192];    // q|k|v per row
__device__ float g_proj[NROW * 128];   // qA|kA per row  ({q,k}@attn_w1)
__device__ float g_w2p[32 * 64];       // tpr_w2 @ attn_w1
__device__ float g_b1a[64];            // tpr_b2 @ attn_w1 + attn_b1

// ---------------------------------------------------------------------------
__global__ __launch_bounds__(192) void qkv_kernel(const float* __restrict__ x,
                                                  const float* __restrict__ w) {
    __shared__ float xs[128];
    const int row = blockIdx.x;
    const int tid = threadIdx.x;
    if (tid < 128) xs[tid] = x[row * 128 + tid];
    __syncthreads();
    float a0 = 0.f, a1 = 0.f, a2 = 0.f, a3 = 0.f;
#pragma unroll 8
    for (int d = 0; d < 128; d += 4) {
        a0 += xs[d + 0] * w[(d + 0) * 192 + tid];
        a1 += xs[d + 1] * w[(d + 1) * 192 + tid];
        a2 += xs[d + 2] * w[(d + 2) * 192 + tid];
        a3 += xs[d + 3] * w[(d + 3) * 192 + tid];
    }
    g_qkv[row * 192 + tid] = (a0 + a1) + (a2 + a3);
}

__global__ __launch_bounds__(128) void proj_kernel(const float* __restrict__ aw1) {
    __shared__ float qk[128];
    const int row = blockIdx.x;
    const int tid = threadIdx.x;
    qk[tid] = g_qkv[row * 192 + tid];
    __syncthreads();
    const float* src = (tid < 64) ? qk : (qk + 64);
    const int col = tid & 63;
    float a0 = 0.f, a1 = 0.f;
#pragma unroll 8
    for (int d = 0; d < 64; d += 2) {
        a0 += src[d + 0] * aw1[(d + 0) * 64 + col];
        a1 += src[d + 1] * aw1[(d + 1) * 64 + col];
    }
    g_proj[row * 128 + tid] = a0 + a1;
}

__global__ __launch_bounds__(64) void w2p_kernel(const float* __restrict__ tpr_w2,
                                                 const float* __restrict__ tpr_b2,
                                                 const float* __restrict__ aw1,
                                                 const float* __restrict__ ab1) {
    __shared__ float w2s[2048];
    __shared__ float a1s[4096];
    const int tid = threadIdx.x;
    for (int i = tid; i < 2048; i += 64) w2s[i] = tpr_w2[i];
    for (int i = tid; i < 4096; i += 64) a1s[i] = aw1[i];
    __syncthreads();
    const int c = tid;
    for (int h = 0; h < 32; h++) {
        float acc = 0.f;
#pragma unroll 8
        for (int d = 0; d < 64; d++) acc += w2s[h * 64 + d] * a1s[d * 64 + c];
        g_w2p[h * 64 + c] = acc;
    }
    float accb = ab1[c];
#pragma unroll 8
    for (int d = 0; d < 64; d++) accb += tpr_b2[d] * a1s[d * 64 + c];
    g_b1a[c] = accb;
}

// ---------------------------------------------------------------------------
// helpers
// ---------------------------------------------------------------------------
__device__ __forceinline__ void mma_bf16(float* d, const uint32_t* a,
                                         uint32_t b0, uint32_t b1) {
    asm volatile(
        "mma.sync.aligned.m16n8k16.row.col.f32.bf16.bf16.f32 "
        "{%0,%1,%2,%3}, {%4,%5,%6,%7}, {%8,%9}, {%0,%1,%2,%3};"
        : "+f"(d[0]), "+f"(d[1]), "+f"(d[2]), "+f"(d[3])
        : "r"(a[0]), "r"(a[1]), "r"(a[2]), "r"(a[3]), "r"(b0), "r"(b1));
}

__device__ __forceinline__ void ldsm_x4(uint32_t& r0, uint32_t& r1,
                                        uint32_t& r2, uint32_t& r3, uint32_t addr) {
    asm volatile("ldmatrix.sync.aligned.m8n8.x4.shared.b16 {%0,%1,%2,%3}, [%4];"
                 : "=r"(r0), "=r"(r1), "=r"(r2), "=r"(r3) : "r"(addr));
}

__device__ __forceinline__ uint32_t b2u(__nv_bfloat162 v) {
    return *reinterpret_cast<uint32_t*>(&v);
}

__device__ __forceinline__ void split2(float x, float y, uint32_t& hi, uint32_t& lo) {
    __nv_bfloat16 hx = __float2bfloat16_rn(x);
    __nv_bfloat16 hy = __float2bfloat16_rn(y);
    float rx = x - __bfloat162float(hx);
    float ry = y - __bfloat162float(hy);
    __nv_bfloat162 h2; h2.x = hx; h2.y = hy;
    hi = b2u(h2);
    lo = b2u(__floats2bfloat162_rn(rx, ry));
}

__device__ __forceinline__ void split1(float x, __nv_bfloat16& hi, __nv_bfloat16& lo) {
    hi = __float2bfloat16_rn(x);
    lo = __float2bfloat16_rn(x - __bfloat162float(hi));
}

// 4 n-tiles, 3-term bf16x3 split, dependency distance 4 (12 MMAs)
#define MMA_GROUP4(ACC, T0, AH, AL, WHI, WLO, STRIDE, KOFF)                       \
    do {                                                                          \
        uint32_t bh[8], bl[8];                                                    \
        ldsm_x4(bh[0], bh[1], bh[2], bh[3],                                       \
                WHI + (uint32_t)((((T0) * 8 + brow) * (STRIDE)) + (KOFF) + bcol) * 2u); \
        ldsm_x4(bh[4], bh[5], bh[6], bh[7],                                       \
                WHI + (uint32_t)(((((T0) + 2) * 8 + brow) * (STRIDE)) + (KOFF) + bcol) * 2u); \
        ldsm_x4(bl[0], bl[1], bl[2], bl[3],                                       \
                WLO + (uint32_t)((((T0) * 8 + brow) * (STRIDE)) + (KOFF) + bcol) * 2u); \
        ldsm_x4(bl[4], bl[5], bl[6], bl[7],                                       \
                WLO + (uint32_t)(((((T0) + 2) * 8 + brow) * (STRIDE)) + (KOFF) + bcol) * 2u); \
        mma_bf16(ACC[(T0) + 0], AH, bh[0], bh[1]);                                \
        mma_bf16(ACC[(T0) + 1], AH, bh[2], bh[3]);                                \
        mma_bf16(ACC[(T0) + 2], AH, bh[4], bh[5]);                                \
        mma_bf16(ACC[(T0) + 3], AH, bh[6], bh[7]);                                \
        mma_bf16(ACC[(T0) + 0], AH, bl[0], bl[1]);                                \
        mma_bf16(ACC[(T0) + 1], AH, bl[2], bl[3]);                                \
        mma_bf16(ACC[(T0) + 2], AH, bl[4], bl[5]);                                \
        mma_bf16(ACC[(T0) + 3], AH, bl[6], bl[7]);                                \
        mma_bf16(ACC[(T0) + 0], AL, bh[0], bh[1]);                                \
        mma_bf16(ACC[(T0) + 1], AL, bh[2], bh[3]);                                \
        mma_bf16(ACC[(T0) + 2], AL, bh[4], bh[5]);                                \
        mma_bf16(ACC[(T0) + 3], AL, bh[6], bh[7]);                                \
    } while (0)

// ---------------------------------------------------------------------------
// Shared memory byte offsets (16B aligned)
// ---------------------------------------------------------------------------
#define SO_WRE_HI 0          // [64][40] bf16  W2T^T
#define SO_WRE_LO 5120
#define SO_WS1_HI 10240      // [64][40] bf16  W2P^T
#define SO_WS1_LO 15360
#define SO_WAT_HI 20480      // [64][72] bf16  W2A^T
#define SO_WAT_LO 29696
#define SO_S1X_HI 38912      // [64][72] bf16  S1 exchange
#define SO_S1X_LO 48128
#define SO_CL     38912      // combine partials (alias S1X; used post-loop)
#define SO_CA     47232      // 32*65 fp32 each
#define SO_RT_HI  57344      // [64][24] bf16  r tile (k padded 16)
#define SO_RT_LO  60416
#define SO_W1T_HI 63488      // [32][24] bf16  BN-folded W1^T
#define SO_W1T_LO 65024
#define SO_VJ     66560      // [64][36] fp32  vj cols 0..31 exchange
#define SO_B1F    75776      // 32 fp32
#define SO_B2F    75904      // 64
#define SO_B1A    76160      // 64
#define SO_QA     76416      // 64
#define SMEM_BYTES 76672

__global__ __launch_bounds__(256, 2) void va_kernel(
    const float* __restrict__ r,
    const float* __restrict__ tpr_w1, const float* __restrict__ tpr_b1,
    const float* __restrict__ bn_g, const float* __restrict__ bn_b,
    const float* __restrict__ bn_m, const float* __restrict__ bn_v,
    const float* __restrict__ tpr_w2, const float* __restrict__ tpr_b2,
    const float* __restrict__ aw2, float* __restrict__ out)
{
    extern __shared__ __align__(16) char sb[];
    __nv_bfloat16* RT_HI  = (__nv_bfloat16*)(sb + SO_RT_HI);
    __nv_bfloat16* RT_LO  = (__nv_bfloat16*)(sb + SO_RT_LO);
    __nv_bfloat16* W1T_HI = (__nv_bfloat16*)(sb + SO_W1T_HI);
    __nv_bfloat16* W1T_LO = (__nv_bfloat16*)(sb + SO_W1T_LO);
    __nv_bfloat16* WRE_HI = (__nv_bfloat16*)(sb + SO_WRE_HI);
    __nv_bfloat16* WRE_LO = (__nv_bfloat16*)(sb + SO_WRE_LO);
    __nv_bfloat16* WS1_HI = (__nv_bfloat16*)(sb + SO_WS1_HI);
    __nv_bfloat16* WS1_LO = (__nv_bfloat16*)(sb + SO_WS1_LO);
    __nv_bfloat16* WAT_HI = (__nv_bfloat16*)(sb + SO_WAT_HI);
    __nv_bfloat16* WAT_LO = (__nv_bfloat16*)(sb + SO_WAT_LO);
    __nv_bfloat16* S1X_HI = (__nv_bfloat16*)(sb + SO_S1X_HI);
    __nv_bfloat16* S1X_LO = (__nv_bfloat16*)(sb + SO_S1X_LO);
    float* CL   = (float*)(sb + SO_CL);
    float* CA   = (float*)(sb + SO_CA);
    float* VJ   = (float*)(sb + SO_VJ);
    float* B1F  = (float*)(sb + SO_B1F);
    float* B2F  = (float*)(sb + SO_B2F);
    float* B1A  = (float*)(sb + SO_B1A);
    float* QA   = (float*)(sb + SO_QA);

    const int tid = threadIdx.x;
    const int wid = tid >> 5, lane = tid & 31;
    const int gid = lane >> 2, tig = lane & 3;
    const int arow = lane & 7, asel = lane >> 3;

    // ---- stage weights ONCE per persistent CTA ----
    for (int idx = tid; idx < 64 * 24; idx += 256) { RT_HI[idx] = __nv_bfloat16(0.f); RT_LO[idx] = __nv_bfloat16(0.f); }
    for (int idx = tid; idx < 32 * 24; idx += 256) { W1T_HI[idx] = __nv_bfloat16(0.f); W1T_LO[idx] = __nv_bfloat16(0.f); }
    if (tid < 32) {
        float sc = bn_g[tid] * rsqrtf(bn_v[tid] + BN_EPS);
        B1F[tid] = (tpr_b1[tid] - bn_m[tid]) * sc + bn_b[tid];
    }
    if (tid < 64) {
        B2F[tid] = tpr_b2[tid];
        B1A[tid] = g_b1a[tid];
    }
    __syncthreads();
    for (int idx = tid; idx < 288; idx += 256) {      // BN-folded W1^T
        const int d = idx >> 5, n = idx & 31;
        const float sc = bn_g[n] * rsqrtf(bn_v[n] + BN_EPS);
        __nv_bfloat16 hi, lo;
        split1(tpr_w1[idx] * sc, hi, lo);
        W1T_HI[n * 24 + d] = hi;
        W1T_LO[n * 24 + d] = lo;
    }
    for (int idx = tid; idx < 2048; idx += 256) {     // W2T^T, W2P^T (stride 40)
        const int n = idx >> 5, k = idx & 31;
        __nv_bfloat16 hi, lo;
        split1(tpr_w2[k * 64 + n], hi, lo);
        WRE_HI[n * 40 + k] = hi; WRE_LO[n * 40 + k] = lo;
        split1(g_w2p[k * 64 + n], hi, lo);
        WS1_HI[n * 40 + k] = hi; WS1_LO[n * 40 + k] = lo;
    }
    for (int idx = tid; idx < 4096; idx += 256) {     // W2A^T (stride 72)
        const int n = idx >> 6, k = idx & 63;
        __nv_bfloat16 hi, lo;
        split1(aw2[k * 64 + n], hi, lo);
        WAT_HI[n * 72 + k] = hi; WAT_LO[n * 72 + k] = lo;
    }

    const int wmod = wid & 3;            // m-tile (warps w and w+4 share it)
    const int nq = wid >> 2;             // n-half owner for Sim phase
    const int m0 = wmod * 16;
    const int r0 = m0 + gid;
    const int brow = arow + (asel >> 1) * 8;
    const int bcol = (asel & 1) * 8;
    const int aoff24 = (m0 + arow + (asel & 1) * 8) * 24 + (asel >> 1) * 8;
    const int aoff72 = (m0 + arow + (asel & 1) * 8) * 72 + (asel >> 1) * 8;

    const uint32_t RThi_a  = (uint32_t)__cvta_generic_to_shared(RT_HI);
    const uint32_t RTlo_a  = (uint32_t)__cvta_generic_to_shared(RT_LO);
    const uint32_t W1Thi_a = (uint32_t)__cvta_generic_to_shared(W1T_HI);
    const uint32_t W1Tlo_a = (uint32_t)__cvta_generic_to_shared(W1T_LO);
    const uint32_t WS1hi_a = (uint32_t)__cvta_generic_to_shared(WS1_HI);
    const uint32_t WS1lo_a = (uint32_t)__cvta_generic_to_shared(WS1_LO);
    const uint32_t WREhi_a = (uint32_t)__cvta_generic_to_shared(WRE_HI);
    const uint32_t WRElo_a = (uint32_t)__cvta_generic_to_shared(WRE_LO);
    const uint32_t WAThi_a = (uint32_t)__cvta_generic_to_shared(WAT_HI) + (uint32_t)(nq * 32 * 72 * 2);
    const uint32_t WATlo_a = (uint32_t)__cvta_generic_to_shared(WAT_LO) + (uint32_t)(nq * 32 * 72 * 2);
    const uint32_t S1Xhi_a = (uint32_t)__cvta_generic_to_shared(S1X_HI);
    const uint32_t S1Xlo_a = (uint32_t)__cvta_generic_to_shared(S1X_LO);

    for (int row = blockIdx.x; row < NROW; row += GRID_PERS) {
        const int b = row >> 8;
        if (tid < 64) QA[tid] = g_proj[row * 128 + tid];

        float l8[8], a8[8];
#pragma unroll
        for (int s = 0; s < 8; s++) { l8[s] = 0.f; a8[s] = 0.f; }

        const float* rrow = r + (size_t)row * (TT * 9);

        for (int jt = 0; jt < 4; jt++) {
            const int j0 = jt * 64;
            // ---- stage r tile as split bf16 ----
            for (int idx = tid; idx < 576; idx += 256) {
                const int j = idx / 9, d = idx - j * 9;
                __nv_bfloat16 hi, lo;
                split1(rrow[j0 * 9 + idx], hi, lo);
                RT_HI[j * 24 + d] = hi;
                RT_LO[j * 24 + d] = lo;
            }
            __syncthreads();                                   // sync1

            // ---- Phase A (regs, every warp): H = relu(r @ W1F + B1F) ----
            uint32_t Hhi[2][4], Hlo[2][4];
            {
                uint32_t rahi[4], ralo[4];
                ldsm_x4(rahi[0], rahi[1], rahi[2], rahi[3], RThi_a + (uint32_t)aoff24 * 2u);
                ldsm_x4(ralo[0], ralo[1], ralo[2], ralo[3], RTlo_a + (uint32_t)aoff24 * 2u);
                float accA[4][4];
#pragma unroll
                for (int t = 0; t < 4; t++)
#pragma unroll
                    for (int u = 0; u < 4; u++) accA[t][u] = 0.f;
                MMA_GROUP4(accA, 0, rahi, ralo, W1Thi_a, W1Tlo_a, 24, 0);
#pragma unroll
                for (int ks = 0; ks < 2; ks++) {
                    const int t0 = 2 * ks, t1 = 2 * ks + 1;
                    const float2 bb0 = *(const float2*)(B1F + t0 * 8 + 2 * tig);
                    const float2 bb1 = *(const float2*)(B1F + t1 * 8 + 2 * tig);
                    split2(fmaxf(accA[t0][0] + bb0.x, 0.f), fmaxf(accA[t0][1] + bb0.y, 0.f),
                           Hhi[ks][0], Hlo[ks][0]);
                    split2(fmaxf(accA[t0][2] + bb0.x, 0.f), fmaxf(accA[t0][3] + bb0.y, 0.f),
                           Hhi[ks][1], Hlo[ks][1]);
                    split2(fmaxf(accA[t1][0] + bb1.x, 0.f), fmaxf(accA[t1][1] + bb1.y, 0.f),
                           Hhi[ks][2], Hlo[ks][2]);
                    split2(fmaxf(accA[t1][2] + bb1.x, 0.f), fmaxf(accA[t1][3] + bb1.y, 0.f),
                           Hhi[ks][3], Hlo[ks][3]);
                }
            }

            uint32_t s1hi[4][4], s1lo[4][4];   // S1 A-frags (k=64)
            float vjk[4][4];                   // warps 4-7: vj cols 32..63
            if (wid < 4) {
                // ---- warps 0-3: S1 = relu(H@W2P + qa - ka + b1a) ----
                float accS[8][4];
#pragma unroll
                for (int t = 0; t < 8; t++)
#pragma unroll
                    for (int u = 0; u < 4; u++) accS[t][u] = 0.f;
#pragma unroll
                for (int g = 0; g < 2; g++)
#pragma unroll
                    for (int ks = 0; ks < 2; ks++)
                        MMA_GROUP4(accS, g * 4, Hhi[ks], Hlo[ks], WS1hi_a, WS1lo_a, 40, ks * 16);
                const float* ka0p = &g_proj[(b * TT + j0 + r0) * 128 + 64];
                const float* ka1p = &g_proj[(b * TT + j0 + r0 + 8) * 128 + 64];
#pragma unroll
                for (int kg = 0; kg < 4; kg++) {
#pragma unroll
                    for (int half = 0; half < 2; half++) {
                        const int tt = 2 * kg + half;
                        const int c = tt * 8 + 2 * tig;
                        const float2 qa2 = *(const float2*)(QA + c);
                        const float2 ba2 = *(const float2*)(B1A + c);
                        const float2 ka0 = *(const float2*)(ka0p + c);
                        const float2 ka1 = *(const float2*)(ka1p + c);
                        const float s00 = fmaxf(accS[tt][0] + qa2.x - ka0.x + ba2.x, 0.f);
                        const float s01 = fmaxf(accS[tt][1] + qa2.y - ka0.y + ba2.y, 0.f);
                        const float s10 = fmaxf(accS[tt][2] + qa2.x - ka1.x + ba2.x, 0.f);
                        const float s11 = fmaxf(accS[tt][3] + qa2.y - ka1.y + ba2.y, 0.f);
                        uint32_t hi0, lo0, hi1, lo1;
                        split2(s00, s01, hi0, lo0);
                        split2(s10, s11, hi1, lo1);
                        s1hi[kg][half * 2] = hi0;     s1lo[kg][half * 2] = lo0;
                        s1hi[kg][half * 2 + 1] = hi1; s1lo[kg][half * 2 + 1] = lo1;
                        *(uint32_t*)(S1X_HI + r0 * 72 + c) = hi0;
                        *(uint32_t*)(S1X_LO + r0 * 72 + c) = lo0;
                        *(uint32_t*)(S1X_HI + (r0 + 8) * 72 + c) = hi1;
                        *(uint32_t*)(S1X_LO + (r0 + 8) * 72 + c) = lo1;
                    }
                }
            } else {
                // ---- warps 4-7: RE = H@W2T + b2f ; vj = RE + vg ----
                float accR[8][4];
#pragma unroll
                for (int t = 0; t < 8; t++)
#pragma unroll
                    for (int u = 0; u < 4; u++) accR[t][u] = 0.f;
#pragma unroll
                for (int g = 0; g < 2; g++)
#pragma unroll
                    for (int ks = 0; ks < 2; ks++)
                        MMA_GROUP4(accR, g * 4, Hhi[ks], Hlo[ks], WREhi_a, WRElo_a, 40, ks * 16);
                const float* v0p = &g_qkv[(b * TT + j0 + r0) * 192 + 128];
                const float* v1p = &g_qkv[(b * TT + j0 + r0 + 8) * 192 + 128];
#pragma unroll
                for (int tt = 0; tt < 8; tt++) {
                    const int c = tt * 8 + 2 * tig;
                    const float2 bf2 = *(const float2*)(B2F + c);
                    const float2 vg0 = *(const float2*)(v0p + c);
                    const float2 vg1 = *(const float2*)(v1p + c);
                    const float j00 = accR[tt][0] + bf2.x + vg0.x;
                    const float j01 = accR[tt][1] + bf2.y + vg0.y;
                    const float j10 = accR[tt][2] + bf2.x + vg1.x;
                    const float j11 = accR[tt][3] + bf2.y + vg1.y;
                    if (tt < 4) {            // cols 0..31 -> smem for warps 0-3
                        *(float2*)(VJ + r0 * 36 + c) = make_float2(j00, j01);
                        *(float2*)(VJ + (r0 + 8) * 36 + c) = make_float2(j10, j11);
                    } else {                 // cols 32..63 stay local
                        vjk[tt - 4][0] = j00; vjk[tt - 4][1] = j01;
                        vjk[tt - 4][2] = j10; vjk[tt - 4][3] = j11;
                    }
                }
            }
            __syncthreads();                                   // sync2

            // ---- Sim = S1 @ W2A, all 8 warps, n-half nq each ----
            float accD[4][4];
            {
                if (wid >= 4) {
#pragma unroll
                    for (int ks = 0; ks < 4; ks++) {
                        ldsm_x4(s1hi[ks][0], s1hi[ks][1], s1hi[ks][2], s1hi[ks][3],
                                S1Xhi_a + (uint32_t)(aoff72 + ks * 16) * 2u);
                        ldsm_x4(s1lo[ks][0], s1lo[ks][1], s1lo[ks][2], s1lo[ks][3],
                                S1Xlo_a + (uint32_t)(aoff72 + ks * 16) * 2u);
                    }
                }
#pragma unroll
                for (int t = 0; t < 4; t++)
#pragma unroll
                    for (int u = 0; u < 4; u++) accD[t][u] = 0.f;
#pragma unroll
                for (int ks = 0; ks < 4; ks++)
                    MMA_GROUP4(accD, 0, s1hi[ks], s1lo[ks], WAThi_a, WATlo_a, 72, ks * 16);
            }

            // ---- softmax accumulate in fragment layout (no barrier) ----
#pragma unroll
            for (int tt = 0; tt < 4; tt++) {
                float vj00, vj01, vj10, vj11;
                if (wid < 4) {
                    const int c = tt * 8 + 2 * tig;
                    const float2 a0v = *(const float2*)(VJ + r0 * 36 + c);
                    const float2 a1v = *(const float2*)(VJ + (r0 + 8) * 36 + c);
                    vj00 = a0v.x; vj01 = a0v.y; vj10 = a1v.x; vj11 = a1v.y;
                } else {
                    vj00 = vjk[tt][0]; vj01 = vjk[tt][1];
                    vj10 = vjk[tt][2]; vj11 = vjk[tt][3];
                }
                const float e00 = __expf(accD[tt][0]);
                const float e01 = __expf(accD[tt][1]);
                const float e10 = __expf(accD[tt][2]);
                const float e11 = __expf(accD[tt][3]);
                l8[tt * 2 + 0] += e00 + e10;
                l8[tt * 2 + 1] += e01 + e11;
                a8[tt * 2 + 0] += e00 * vj00 + e10 * vj10;
                a8[tt * 2 + 1] += e01 * vj01 + e11 * vj11;
            }
        }

        // ---- cross-warp combine (CL/CA alias S1X space) ----
        __syncthreads();           // all S1X/VJ reads of last tile done
        {
            const int p = wmod * 8 + gid;
#pragma unroll
            for (int tt = 0; tt < 4; tt++) {
#pragma unroll
                for (int u = 0; u < 2; u++) {
                    const int c = nq * 32 + tt * 8 + 2 * tig + u;
                    CL[p * 65 + c] = l8[tt * 2 + u];
                    CA[p * 65 + c] = a8[tt * 2 + u];
                }
            }
        }
        __syncthreads();
        if (tid < 64) {
            float L = 0.f, A = 0.f;
#pragma unroll
            for (int pp = 0; pp < 32; pp++) {
                L += CL[pp * 65 + tid];
                A += CA[pp * 65 + tid];
            }
            out[row * 64 + tid] = A / L;
        }
        __syncthreads();           // CL/CA reads done before next row's S1X writes
    }
}

// ---------------------------------------------------------------------------
extern "C" void kernel_launch(void* const* d_in, const int* in_sizes, int n_in,
                              void* d_out, int out_size) {
    (void)in_sizes; (void)n_in; (void)out_size;
    const float* x      = (const float*)d_in[0];
    const float* r      = (const float*)d_in[1];
    const float* w_qkv  = (const float*)d_in[2];
    const float* tpr_w1 = (const float*)d_in[3];
    const float* tpr_b1 = (const float*)d_in[4];
    const float* bn_g   = (const float*)d_in[5];
    const float* bn_b   = (const float*)d_in[6];
    const float* bn_m   = (const float*)d_in[7];
    const float* bn_v   = (const float*)d_in[8];
    const float* tpr_w2 = (const float*)d_in[9];
    const float* tpr_b2 = (const float*)d_in[10];
    const float* aw1    = (const float*)d_in[11];
    const float* ab1    = (const float*)d_in[12];
    const float* aw2    = (const float*)d_in[13];
    float* out = (float*)d_out;

    cudaFuncSetAttribute(va_kernel, cudaFuncAttributeMaxDynamicSharedMemorySize,
                         SMEM_BYTES);

    qkv_kernel<<<NROW, 192>>>(x, w_qkv);
    proj_kernel<<<NROW, 128>>>(aw1);
    w2p_kernel<<<1, 64>>>(tpr_w2, tpr_b2, aw1, ab1);
    va_kernel<<<GRID_PERS, 256, SMEM_BYTES>>>(r, tpr_w1, tpr_b1, bn_g, bn_b, bn_m,
                                              bn_v, tpr_w2, tpr_b2, aw2, out);
}

// round 10
// speedup vs baseline: 2.2259x; 1.0408x over previous
#include <cuda_runtime.h>
#include <cuda_bf16.h>
#include <math.h>
#include <stdint.h>

#define TT 256
#define NROW 2048            // B*T
#define BN_EPS 1e-5f
#define GRID_PERS 296        // 148 SMs x 2 CTAs = one full wave

// scratch
__device__ float g_qkv[NROW * 192];    // q|k|v per row
__device__ float g_proj[NROW * 128];   // qA|kA per row  ({q,k}@attn_w1)
__device__ float g_w2p[32 * 64];       // tpr_w2 @ attn_w1
__device__ float g_b1a[64];            // tpr_b2 @ attn_w1 + attn_b1

// ---------------------------------------------------------------------------
__global__ __launch_bounds__(192) void qkv_kernel(const float* __restrict__ x,
                                                  const float* __restrict__ w) {
    __shared__ float xs[128];
    const int row = blockIdx.x;
    const int tid = threadIdx.x;
    if (tid < 128) xs[tid] = x[row * 128 + tid];
    __syncthreads();
    float a0 = 0.f, a1 = 0.f, a2 = 0.f, a3 = 0.f;
#pragma unroll 8
    for (int d = 0; d < 128; d += 4) {
        a0 += xs[d + 0] * w[(d + 0) * 192 + tid];
        a1 += xs[d + 1] * w[(d + 1) * 192 + tid];
        a2 += xs[d + 2] * w[(d + 2) * 192 + tid];
        a3 += xs[d + 3] * w[(d + 3) * 192 + tid];
    }
    g_qkv[row * 192 + tid] = (a0 + a1) + (a2 + a3);
}

__global__ __launch_bounds__(128) void proj_kernel(const float* __restrict__ aw1) {
    __shared__ float qk[128];
    const int row = blockIdx.x;
    const int tid = threadIdx.x;
    qk[tid] = g_qkv[row * 192 + tid];
    __syncthreads();
    const float* src = (tid < 64) ? qk : (qk + 64);
    const int col = tid & 63;
    float a0 = 0.f, a1 = 0.f;
#pragma unroll 8
    for (int d = 0; d < 64; d += 2) {
        a0 += src[d + 0] * aw1[(d + 0) * 64 + col];
        a1 += src[d + 1] * aw1[(d + 1) * 64 + col];
    }
    g_proj[row * 128 + tid] = a0 + a1;
}

__global__ __launch_bounds__(64) void w2p_kernel(const float* __restrict__ tpr_w2,
                                                 const float* __restrict__ tpr_b2,
                                                 const float* __restrict__ aw1,
                                                 const float* __restrict__ ab1) {
    __shared__ float w2s[2048];
    __shared__ float a1s[4096];
    const int tid = threadIdx.x;
    for (int i = tid; i < 2048; i += 64) w2s[i] = tpr_w2[i];
    for (int i = tid; i < 4096; i += 64) a1s[i] = aw1[i];
    __syncthreads();
    const int c = tid;
    for (int h = 0; h < 32; h++) {
        float acc = 0.f;
#pragma unroll 8
        for (int d = 0; d < 64; d++) acc += w2s[h * 64 + d] * a1s[d * 64 + c];
        g_w2p[h * 64 + c] = acc;
    }
    float accb = ab1[c];
#pragma unroll 8
    for (int d = 0; d < 64; d++) accb += tpr_b2[d] * a1s[d * 64 + c];
    g_b1a[c] = accb;
}

// ---------------------------------------------------------------------------
// helpers
// ---------------------------------------------------------------------------
__device__ __forceinline__ void mma_bf16(float* d, const uint32_t* a,
                                         uint32_t b0, uint32_t b1) {
    asm volatile(
        "mma.sync.aligned.m16n8k16.row.col.f32.bf16.bf16.f32 "
        "{%0,%1,%2,%3}, {%4,%5,%6,%7}, {%8,%9}, {%0,%1,%2,%3};"
        : "+f"(d[0]), "+f"(d[1]), "+f"(d[2]), "+f"(d[3])
        : "r"(a[0]), "r"(a[1]), "r"(a[2]), "r"(a[3]), "r"(b0), "r"(b1));
}

__device__ __forceinline__ void ldsm_x4(uint32_t& r0, uint32_t& r1,
                                        uint32_t& r2, uint32_t& r3, uint32_t addr) {
    asm volatile("ldmatrix.sync.aligned.m8n8.x4.shared.b16 {%0,%1,%2,%3}, [%4];"
                 : "=r"(r0), "=r"(r1), "=r"(r2), "=r"(r3) : "r"(addr));
}

#define BAR_ARRIVE(id) asm volatile("bar.arrive %0, %1;" :: "r"(id), "r"(256) : "memory")
#define BAR_SYNC(id)   asm volatile("bar.sync %0, %1;"   :: "r"(id), "r"(256) : "memory")

__device__ __forceinline__ uint32_t b2u(__nv_bfloat162 v) {
    return *reinterpret_cast<uint32_t*>(&v);
}

__device__ __forceinline__ void split2(float x, float y, uint32_t& hi, uint32_t& lo) {
    __nv_bfloat16 hx = __float2bfloat16_rn(x);
    __nv_bfloat16 hy = __float2bfloat16_rn(y);
    float rx = x - __bfloat162float(hx);
    float ry = y - __bfloat162float(hy);
    __nv_bfloat162 h2; h2.x = hx; h2.y = hy;
    hi = b2u(h2);
    lo = b2u(__floats2bfloat162_rn(rx, ry));
}

__device__ __forceinline__ void split1(float x, __nv_bfloat16& hi, __nv_bfloat16& lo) {
    hi = __float2bfloat16_rn(x);
    lo = __float2bfloat16_rn(x - __bfloat162float(hi));
}

// 4 n-tiles, 3-term bf16x3 split, dependency distance 4 (12 MMAs)
#define MMA_GROUP4(ACC, T0, AH, AL, WHI, WLO, STRIDE, KOFF)                       \
    do {                                                                          \
        uint32_t bh[8], bl[8];                                                    \
        ldsm_x4(bh[0], bh[1], bh[2], bh[3],                                       \
                WHI + (uint32_t)((((T0) * 8 + brow) * (STRIDE)) + (KOFF) + bcol) * 2u); \
        ldsm_x4(bh[4], bh[5], bh[6], bh[7],                                       \
                WHI + (uint32_t)(((((T0) + 2) * 8 + brow) * (STRIDE)) + (KOFF) + bcol) * 2u); \
        ldsm_x4(bl[0], bl[1], bl[2], bl[3],                                       \
                WLO + (uint32_t)((((T0) * 8 + brow) * (STRIDE)) + (KOFF) + bcol) * 2u); \
        ldsm_x4(bl[4], bl[5], bl[6], bl[7],                                       \
                WLO + (uint32_t)(((((T0) + 2) * 8 + brow) * (STRIDE)) + (KOFF) + bcol) * 2u); \
        mma_bf16(ACC[(T0) + 0], AH, bh[0], bh[1]);                                \
        mma_bf16(ACC[(T0) + 1], AH, bh[2], bh[3]);                                \
        mma_bf16(ACC[(T0) + 2], AH, bh[4], bh[5]);                                \
        mma_bf16(ACC[(T0) + 3], AH, bh[6], bh[7]);                                \
        mma_bf16(ACC[(T0) + 0], AH, bl[0], bl[1]);                                \
        mma_bf16(ACC[(T0) + 1], AH, bl[2], bl[3]);                                \
        mma_bf16(ACC[(T0) + 2], AH, bl[4], bl[5]);                                \
        mma_bf16(ACC[(T0) + 3], AH, bl[6], bl[7]);                                \
        mma_bf16(ACC[(T0) + 0], AL, bh[0], bh[1]);                                \
        mma_bf16(ACC[(T0) + 1], AL, bh[2], bh[3]);                                \
        mma_bf16(ACC[(T0) + 2], AL, bh[4], bh[5]);                                \
        mma_bf16(ACC[(T0) + 3], AL, bh[6], bh[7]);                                \
    } while (0)

// ---------------------------------------------------------------------------
// Shared memory byte offsets (16B aligned)
// ---------------------------------------------------------------------------
#define SO_WRE_HI 0          // [64][40] bf16  W2T^T
#define SO_WRE_LO 5120
#define SO_WS1_HI 10240      // [64][40] bf16  W2P^T
#define SO_WS1_LO 15360
#define SO_WAT_HI 20480      // [64][72] bf16  W2A^T
#define SO_WAT_LO 29696
#define SO_S1X_HI 38912      // [64][72] bf16  S1 exchange
#define SO_S1X_LO 48128
#define SO_CL     38912      // combine partials (alias S1X; used post-loop)
#define SO_CA     47232      // 32*65 fp32 each
#define SO_RT_HI  57344      // [64][24] bf16  r tile (k padded 16)
#define SO_RT_LO  60416
#define SO_W1T_HI 63488      // [32][24] bf16  BN-folded W1^T
#define SO_W1T_LO 65024
#define SO_VJ     66560      // [64][36] fp32  vj cols 0..31 exchange
#define SO_B1F    75776      // 32 fp32
#define SO_B2F    75904      // 64
#define SO_B1A    76160      // 64
#define SO_QA     76416      // 64
#define SMEM_BYTES 76672

__global__ __launch_bounds__(256, 2) void va_kernel(
    const float* __restrict__ r,
    const float* __restrict__ tpr_w1, const float* __restrict__ tpr_b1,
    const float* __restrict__ bn_g, const float* __restrict__ bn_b,
    const float* __restrict__ bn_m, const float* __restrict__ bn_v,
    const float* __restrict__ tpr_w2, const float* __restrict__ tpr_b2,
    const float* __restrict__ aw2, float* __restrict__ out)
{
    extern __shared__ __align__(16) char sb[];
    __nv_bfloat16* RT_HI  = (__nv_bfloat16*)(sb + SO_RT_HI);
    __nv_bfloat16* RT_LO  = (__nv_bfloat16*)(sb + SO_RT_LO);
    __nv_bfloat16* W1T_HI = (__nv_bfloat16*)(sb + SO_W1T_HI);
    __nv_bfloat16* W1T_LO = (__nv_bfloat16*)(sb + SO_W1T_LO);
    __nv_bfloat16* WRE_HI = (__nv_bfloat16*)(sb + SO_WRE_HI);
    __nv_bfloat16* WRE_LO = (__nv_bfloat16*)(sb + SO_WRE_LO);
    __nv_bfloat16* WS1_HI = (__nv_bfloat16*)(sb + SO_WS1_HI);
    __nv_bfloat16* WS1_LO = (__nv_bfloat16*)(sb + SO_WS1_LO);
    __nv_bfloat16* WAT_HI = (__nv_bfloat16*)(sb + SO_WAT_HI);
    __nv_bfloat16* WAT_LO = (__nv_bfloat16*)(sb + SO_WAT_LO);
    __nv_bfloat16* S1X_HI = (__nv_bfloat16*)(sb + SO_S1X_HI);
    __nv_bfloat16* S1X_LO = (__nv_bfloat16*)(sb + SO_S1X_LO);
    float* CL   = (float*)(sb + SO_CL);
    float* CA   = (float*)(sb + SO_CA);
    float* VJ   = (float*)(sb + SO_VJ);
    float* B1F  = (float*)(sb + SO_B1F);
    float* B2F  = (float*)(sb + SO_B2F);
    float* B1A  = (float*)(sb + SO_B1A);
    float* QA   = (float*)(sb + SO_QA);

    const int tid = threadIdx.x;
    const int wid = tid >> 5, lane = tid & 31;
    const int gid = lane >> 2, tig = lane & 3;
    const int arow = lane & 7, asel = lane >> 3;

    // ---- stage weights ONCE per persistent CTA ----
    for (int idx = tid; idx < 64 * 24; idx += 256) { RT_HI[idx] = __nv_bfloat16(0.f); RT_LO[idx] = __nv_bfloat16(0.f); }
    for (int idx = tid; idx < 32 * 24; idx += 256) { W1T_HI[idx] = __nv_bfloat16(0.f); W1T_LO[idx] = __nv_bfloat16(0.f); }
    if (tid < 32) {
        float sc = bn_g[tid] * rsqrtf(bn_v[tid] + BN_EPS);
        B1F[tid] = (tpr_b1[tid] - bn_m[tid]) * sc + bn_b[tid];
    }
    if (tid < 64) {
        B2F[tid] = tpr_b2[tid];
        B1A[tid] = g_b1a[tid];
    }
    __syncthreads();
    for (int idx = tid; idx < 288; idx += 256) {      // BN-folded W1^T
        const int d = idx >> 5, n = idx & 31;
        const float sc = bn_g[n] * rsqrtf(bn_v[n] + BN_EPS);
        __nv_bfloat16 hi, lo;
        split1(tpr_w1[idx] * sc, hi, lo);
        W1T_HI[n * 24 + d] = hi;
        W1T_LO[n * 24 + d] = lo;
    }
    for (int idx = tid; idx < 2048; idx += 256) {     // W2T^T, W2P^T (stride 40)
        const int n = idx >> 5, k = idx & 31;
        __nv_bfloat16 hi, lo;
        split1(tpr_w2[k * 64 + n], hi, lo);
        WRE_HI[n * 40 + k] = hi; WRE_LO[n * 40 + k] = lo;
        split1(g_w2p[k * 64 + n], hi, lo);
        WS1_HI[n * 40 + k] = hi; WS1_LO[n * 40 + k] = lo;
    }
    for (int idx = tid; idx < 4096; idx += 256) {     // W2A^T (stride 72)
        const int n = idx >> 6, k = idx & 63;
        __nv_bfloat16 hi, lo;
        split1(aw2[k * 64 + n], hi, lo);
        WAT_HI[n * 72 + k] = hi; WAT_LO[n * 72 + k] = lo;
    }

    const int wmod = wid & 3;            // m-tile (warps w and w+4 share it)
    const int nq = wid >> 2;             // n-half owner for Sim phase
    const int m0 = wmod * 16;
    const int r0 = m0 + gid;
    const int brow = arow + (asel >> 1) * 8;
    const int bcol = (asel & 1) * 8;
    const int aoff24 = (m0 + arow + (asel & 1) * 8) * 24 + (asel >> 1) * 8;
    const int aoff72 = (m0 + arow + (asel & 1) * 8) * 72 + (asel >> 1) * 8;

    const uint32_t RThi_a  = (uint32_t)__cvta_generic_to_shared(RT_HI);
    const uint32_t RTlo_a  = (uint32_t)__cvta_generic_to_shared(RT_LO);
    const uint32_t W1Thi_a = (uint32_t)__cvta_generic_to_shared(W1T_HI);
    const uint32_t W1Tlo_a = (uint32_t)__cvta_generic_to_shared(W1T_LO);
    const uint32_t WS1hi_a = (uint32_t)__cvta_generic_to_shared(WS1_HI);
    const uint32_t WS1lo_a = (uint32_t)__cvta_generic_to_shared(WS1_LO);
    const uint32_t WREhi_a = (uint32_t)__cvta_generic_to_shared(WRE_HI);
    const uint32_t WRElo_a = (uint32_t)__cvta_generic_to_shared(WRE_LO);
    const uint32_t WAThi_a = (uint32_t)__cvta_generic_to_shared(WAT_HI) + (uint32_t)(nq * 32 * 72 * 2);
    const uint32_t WATlo_a = (uint32_t)__cvta_generic_to_shared(WAT_LO) + (uint32_t)(nq * 32 * 72 * 2);
    const uint32_t S1Xhi_a = (uint32_t)__cvta_generic_to_shared(S1X_HI);
    const uint32_t S1Xlo_a = (uint32_t)__cvta_generic_to_shared(S1X_LO);

    for (int row = blockIdx.x; row < NROW; row += GRID_PERS) {
        const int b = row >> 8;
        const float* rrow = r + (size_t)row * (TT * 9);

        // ---- stage QA + r tile 0 (prev row's reads all barrier-protected) ----
        if (tid < 64) QA[tid] = g_proj[row * 128 + tid];
        float4 rpre;
        if (tid < 144) rpre = ((const float4*)rrow)[tid];
        if (tid < 144) {
            const int e0 = tid * 4;
#pragma unroll
            for (int u = 0; u < 4; u++) {
                const int e = e0 + u, j = e / 9, d = e - j * 9;
                __nv_bfloat16 hi, lo;
                split1(((const float*)&rpre)[u], hi, lo);
                RT_HI[j * 24 + d] = hi;
                RT_LO[j * 24 + d] = lo;
            }
        }
        __syncthreads();

        float l8[8], a8[8];
#pragma unroll
        for (int s = 0; s < 8; s++) { l8[s] = 0.f; a8[s] = 0.f; }

        for (int jt = 0; jt < 4; jt++) {
            const int j0 = jt * 64;

            // ---- Phase A (regs, every warp): H = relu(r @ W1F + B1F) ----
            uint32_t Hhi[2][4], Hlo[2][4];
            {
                uint32_t rahi[4], ralo[4];
                ldsm_x4(rahi[0], rahi[1], rahi[2], rahi[3], RThi_a + (uint32_t)aoff24 * 2u);
                ldsm_x4(ralo[0], ralo[1], ralo[2], ralo[3], RTlo_a + (uint32_t)aoff24 * 2u);
                // prefetch next r tile while MMAs run
                if (jt < 3 && tid < 144)
                    rpre = ((const float4*)(rrow + (j0 + 64) * 9))[tid];
                float accA[4][4];
#pragma unroll
                for (int t = 0; t < 4; t++)
#pragma unroll
                    for (int u = 0; u < 4; u++) accA[t][u] = 0.f;
                MMA_GROUP4(accA, 0, rahi, ralo, W1Thi_a, W1Tlo_a, 24, 0);
#pragma unroll
                for (int ks = 0; ks < 2; ks++) {
                    const int t0 = 2 * ks, t1 = 2 * ks + 1;
                    const float2 bb0 = *(const float2*)(B1F + t0 * 8 + 2 * tig);
                    const float2 bb1 = *(const float2*)(B1F + t1 * 8 + 2 * tig);
                    split2(fmaxf(accA[t0][0] + bb0.x, 0.f), fmaxf(accA[t0][1] + bb0.y, 0.f),
                           Hhi[ks][0], Hlo[ks][0]);
                    split2(fmaxf(accA[t0][2] + bb0.x, 0.f), fmaxf(accA[t0][3] + bb0.y, 0.f),
                           Hhi[ks][1], Hlo[ks][1]);
                    split2(fmaxf(accA[t1][0] + bb1.x, 0.f), fmaxf(accA[t1][1] + bb1.y, 0.f),
                           Hhi[ks][2], Hlo[ks][2]);
                    split2(fmaxf(accA[t1][2] + bb1.x, 0.f), fmaxf(accA[t1][3] + bb1.y, 0.f),
                           Hhi[ks][3], Hlo[ks][3]);
                }
            }

            float accD[4][4];
#pragma unroll
            for (int t = 0; t < 4; t++)
#pragma unroll
                for (int u = 0; u < 4; u++) accD[t][u] = 0.f;
            float vjk[4][4];                   // warps 4-7: vj cols 32..63

            if (wid < 4) {
                // ---- warps 0-3: S1 = relu(H@W2P + qa - ka + b1a) ----
                float accS[8][4];
#pragma unroll
                for (int t = 0; t < 8; t++)
#pragma unroll
                    for (int u = 0; u < 4; u++) accS[t][u] = 0.f;
#pragma unroll
                for (int g = 0; g < 2; g++)
#pragma unroll
                    for (int ks = 0; ks < 2; ks++)
                        MMA_GROUP4(accS, g * 4, Hhi[ks], Hlo[ks], WS1hi_a, WS1lo_a, 40, ks * 16);
                const float* ka0p = &g_proj[(b * TT + j0 + r0) * 128 + 64];
                const float* ka1p = &g_proj[(b * TT + j0 + r0 + 8) * 128 + 64];
                uint32_t s1hi[4][4], s1lo[4][4];
#pragma unroll
                for (int kg = 0; kg < 4; kg++) {
#pragma unroll
                    for (int half = 0; half < 2; half++) {
                        const int tt = 2 * kg + half;
                        const int c = tt * 8 + 2 * tig;
                        const float2 qa2 = *(const float2*)(QA + c);
                        const float2 ba2 = *(const float2*)(B1A + c);
                        const float2 ka0 = *(const float2*)(ka0p + c);
                        const float2 ka1 = *(const float2*)(ka1p + c);
                        const float s00 = fmaxf(accS[tt][0] + qa2.x - ka0.x + ba2.x, 0.f);
                        const float s01 = fmaxf(accS[tt][1] + qa2.y - ka0.y + ba2.y, 0.f);
                        const float s10 = fmaxf(accS[tt][2] + qa2.x - ka1.x + ba2.x, 0.f);
                        const float s11 = fmaxf(accS[tt][3] + qa2.y - ka1.y + ba2.y, 0.f);
                        uint32_t hi0, lo0, hi1, lo1;
                        split2(s00, s01, hi0, lo0);
                        split2(s10, s11, hi1, lo1);
                        s1hi[kg][half * 2] = hi0;     s1lo[kg][half * 2] = lo0;
                        s1hi[kg][half * 2 + 1] = hi1; s1lo[kg][half * 2 + 1] = lo1;
                        *(uint32_t*)(S1X_HI + r0 * 72 + c) = hi0;
                        *(uint32_t*)(S1X_LO + r0 * 72 + c) = lo0;
                        *(uint32_t*)(S1X_HI + (r0 + 8) * 72 + c) = hi1;
                        *(uint32_t*)(S1X_LO + (r0 + 8) * 72 + c) = lo1;
                    }
                }
                BAR_ARRIVE(1);                 // S1X published
                // Sim immediately from own fragments — no wait on warps 4-7
#pragma unroll
                for (int ks = 0; ks < 4; ks++)
                    MMA_GROUP4(accD, 0, s1hi[ks], s1lo[ks], WAThi_a, WATlo_a, 72, ks * 16);
                BAR_SYNC(2);                   // wait for VJ
            } else {
                // ---- warps 4-7: RE = H@W2T + b2f ; vj = RE + vg ----
                float accR[8][4];
#pragma unroll
                for (int t = 0; t < 8; t++)
#pragma unroll
                    for (int u = 0; u < 4; u++) accR[t][u] = 0.f;
#pragma unroll
                for (int g = 0; g < 2; g++)
#pragma unroll
                    for (int ks = 0; ks < 2; ks++)
                        MMA_GROUP4(accR, g * 4, Hhi[ks], Hlo[ks], WREhi_a, WRElo_a, 40, ks * 16);
                const float* v0p = &g_qkv[(b * TT + j0 + r0) * 192 + 128];
                const float* v1p = &g_qkv[(b * TT + j0 + r0 + 8) * 192 + 128];
#pragma unroll
                for (int tt = 0; tt < 8; tt++) {
                    const int c = tt * 8 + 2 * tig;
                    const float2 bf2 = *(const float2*)(B2F + c);
                    const float2 vg0 = *(const float2*)(v0p + c);
                    const float2 vg1 = *(const float2*)(v1p + c);
                    const float j00 = accR[tt][0] + bf2.x + vg0.x;
                    const float j01 = accR[tt][1] + bf2.y + vg0.y;
                    const float j10 = accR[tt][2] + bf2.x + vg1.x;
                    const float j11 = accR[tt][3] + bf2.y + vg1.y;
                    if (tt < 4) {            // cols 0..31 -> smem for warps 0-3
                        *(float2*)(VJ + r0 * 36 + c) = make_float2(j00, j01);
                        *(float2*)(VJ + (r0 + 8) * 36 + c) = make_float2(j10, j11);
                    } else {                 // cols 32..63 stay local
                        vjk[tt - 4][0] = j00; vjk[tt - 4][1] = j01;
                        vjk[tt - 4][2] = j10; vjk[tt - 4][3] = j11;
                    }
                }
                BAR_ARRIVE(2);                 // VJ published
                BAR_SYNC(1);                   // wait for S1X
                uint32_t s1hi[4][4], s1lo[4][4];
#pragma unroll
                for (int ks = 0; ks < 4; ks++) {
                    ldsm_x4(s1hi[ks][0], s1hi[ks][1], s1hi[ks][2], s1hi[ks][3],
                            S1Xhi_a + (uint32_t)(aoff72 + ks * 16) * 2u);
                    ldsm_x4(s1lo[ks][0], s1lo[ks][1], s1lo[ks][2], s1lo[ks][3],
                            S1Xlo_a + (uint32_t)(aoff72 + ks * 16) * 2u);
                }
#pragma unroll
                for (int ks = 0; ks < 4; ks++)
                    MMA_GROUP4(accD, 0, s1hi[ks], s1lo[ks], WAThi_a, WATlo_a, 72, ks * 16);
            }

            // ---- softmax accumulate in fragment layout ----
#pragma unroll
            for (int tt = 0; tt < 4; tt++) {
                float vj00, vj01, vj10, vj11;
                if (wid < 4) {
                    const int c = tt * 8 + 2 * tig;
                    const float2 a0v = *(const float2*)(VJ + r0 * 36 + c);
                    const float2 a1v = *(const float2*)(VJ + (r0 + 8) * 36 + c);
                    vj00 = a0v.x; vj01 = a0v.y; vj10 = a1v.x; vj11 = a1v.y;
                } else {
                    vj00 = vjk[tt][0]; vj01 = vjk[tt][1];
                    vj10 = vjk[tt][2]; vj11 = vjk[tt][3];
                }
                const float e00 = __expf(accD[tt][0]);
                const float e01 = __expf(accD[tt][1]);
                const float e10 = __expf(accD[tt][2]);
                const float e11 = __expf(accD[tt][3]);
                l8[tt * 2 + 0] += e00 + e10;
                l8[tt * 2 + 1] += e01 + e11;
                a8[tt * 2 + 0] += e00 * vj00 + e10 * vj10;
                a8[tt * 2 + 1] += e01 * vj01 + e11 * vj11;
            }

            // ---- store next r tile (all Phase-A RT reads provably done:
            //      each group's bar.sync waited on the other's post-Phase-A arrive) ----
            if (jt < 3 && tid < 144) {
                const int e0 = tid * 4;
#pragma unroll
                for (int u = 0; u < 4; u++) {
                    const int e = e0 + u, j = e / 9, d = e - j * 9;
                    __nv_bfloat16 hi, lo;
                    split1(((const float*)&rpre)[u], hi, lo);
                    RT_HI[j * 24 + d] = hi;
                    RT_LO[j * 24 + d] = lo;
                }
            }
            __syncthreads();   // guards RT STS vs next ldsm + S1X/VJ reuse
        }

        // ---- cross-warp combine (CL/CA alias S1X space) ----
        {
            const int p = wmod * 8 + gid;
#pragma unroll
            for (int tt = 0; tt < 4; tt++) {
#pragma unroll
                for (int u = 0; u < 2; u++) {
                    const int c = nq * 32 + tt * 8 + 2 * tig + u;
                    CL[p * 65 + c] = l8[tt * 2 + u];
                    CA[p * 65 + c] = a8[tt * 2 + u];
                }
            }
        }
        __syncthreads();
        if (tid < 64) {
            float L = 0.f, A = 0.f;
#pragma unroll
            for (int pp = 0; pp < 32; pp++) {
                L += CL[pp * 65 + tid];
                A += CA[pp * 65 + tid];
            }
            out[row * 64 + tid] = A / L;
        }
        __syncthreads();           // CL/CA reads done before next row's S1X writes
    }
}

// ---------------------------------------------------------------------------
extern "C" void kernel_launch(void* const* d_in, const int* in_sizes, int n_in,
                              void* d_out, int out_size) {
    (void)in_sizes; (void)n_in; (void)out_size;
    const float* x      = (const float*)d_in[0];
    const float* r      = (const float*)d_in[1];
    const float* w_qkv  = (const float*)d_in[2];
    const float* tpr_w1 = (const float*)d_in[3];
    const float* tpr_b1 = (const float*)d_in[4];
    const float* bn_g   = (const float*)d_in[5];
    const float* bn_b   = (const float*)d_in[6];
    const float* bn_m   = (const float*)d_in[7];
    const float* bn_v   = (const float*)d_in[8];
    const float* tpr_w2 = (const float*)d_in[9];
    const float* tpr_b2 = (const float*)d_in[10];
    const float* aw1    = (const float*)d_in[11];
    const float* ab1    = (const float*)d_in[12];
    const float* aw2    = (const float*)d_in[13];
    float* out = (float*)d_out;

    cudaFuncSetAttribute(va_kernel, cudaFuncAttributeMaxDynamicSharedMemorySize,
                         SMEM_BYTES);

    qkv_kernel<<<NROW, 192>>>(x, w_qkv);
    proj_kernel<<<NROW, 128>>>(aw1);
    w2p_kernel<<<1, 64>>>(tpr_w2, tpr_b2, aw1, ab1);
    va_kernel<<<GRID_PERS, 256, SMEM_BYTES>>>(r, tpr_w1, tpr_b1, bn_g, bn_b, bn_m,
                                              bn_v, tpr_w2, tpr_b2, aw2, out);
}